// round 2
// baseline (speedup 1.0000x reference)
#include <cuda_runtime.h>
#include <cstdint>
#include <math.h>

#define B_IMG 8
#define NPROP 4000
#define NCLS 91
#define MAXC (NPROP * (NCLS - 1))   // 360000 per image, hard upper bound
#define NDET 100
#define SMEM_CAP 44032
#define NEGV -1e9f

static __device__ float4        g_box[B_IMG * MAXC];
static __device__ float         g_s[B_IMG * MAXC];
static __device__ unsigned char g_lab[B_IMG * MAXC];
static __device__ int           g_cnt[B_IMG];

__device__ __forceinline__ float load_dim(const int* p) {
    // robust: handles int32/int64 (LE low word) and float32-encoded dims
    int vi = *p;
    if (vi > 0 && vi < 1000000) return (float)vi;
    return __int_as_float(vi);
}

__global__ void zero_cnt_kernel() {
    if (threadIdx.x < B_IMG) g_cnt[threadIdx.x] = 0;
}

// Phase A: one warp per proposal. Softmax over 91 logits, decode only classes
// whose score passes SCORE_THRESH, clip, size-check, compact per-image.
__global__ void phaseA_kernel(const float* __restrict__ logits,
                              const float* __restrict__ reg,
                              const float* __restrict__ props,
                              const int* __restrict__ ph,
                              const int* __restrict__ pw) {
    const int warpsPerBlock = blockDim.x >> 5;
    const int wid  = threadIdx.x >> 5;
    const int lane = threadIdx.x & 31;
    const int p = blockIdx.x * warpsPerBlock + wid;
    if (p >= B_IMG * NPROP) return;

    const float Wf = load_dim(pw);
    const float Hf = load_dim(ph);
    const float CLIPV = 4.135166556742356f;  // log(1000/16)

    const float* z = logits + (size_t)p * NCLS;
    float v0 = z[lane];
    float v1 = z[lane + 32];
    float v2 = (lane < NCLS - 64) ? z[lane + 64] : -INFINITY;
    float m = fmaxf(fmaxf(v0, v1), v2);
    #pragma unroll
    for (int o = 16; o; o >>= 1) m = fmaxf(m, __shfl_xor_sync(0xffffffffu, m, o));
    float e0 = expf(v0 - m), e1 = expf(v1 - m);
    float e2 = (lane < NCLS - 64) ? expf(v2 - m) : 0.0f;
    float ssum = e0 + e1 + e2;
    #pragma unroll
    for (int o = 16; o; o >>= 1) ssum += __shfl_xor_sync(0xffffffffu, ssum, o);

    float px1 = props[p * 4 + 0], py1 = props[p * 4 + 1];
    float px2 = props[p * 4 + 2], py2 = props[p * 4 + 3];
    float w = px2 - px1, h = py2 - py1;
    float cx = px1 + 0.5f * w, cy = py1 + 0.5f * h;

    const int b = p / NPROP;
    const float* rrow = reg + (size_t)p * (NCLS * 4);
    float es[3] = {e0, e1, e2};

    #pragma unroll
    for (int t = 0; t < 3; t++) {
        int c = lane + 32 * t;
        if (c == 0 || c >= NCLS) continue;
        float sc = es[t] / ssum;
        if (!(sc > 0.05f)) continue;
        float r0 = rrow[c * 4 + 0], r1 = rrow[c * 4 + 1];
        float r2 = rrow[c * 4 + 2], r3 = rrow[c * 4 + 3];
        float dx = r0 / 10.0f, dy = r1 / 10.0f;
        float dw = fminf(r2 / 5.0f, CLIPV);
        float dh = fminf(r3 / 5.0f, CLIPV);
        float pcx = dx * w + cx, pcy = dy * h + cy;
        float pwd = expf(dw) * w, phd = expf(dh) * h;
        float x1 = pcx - 0.5f * pwd, y1 = pcy - 0.5f * phd;
        float x2 = pcx + 0.5f * pwd, y2 = pcy + 0.5f * phd;
        x1 = fminf(fmaxf(x1, 0.0f), Wf); x2 = fminf(fmaxf(x2, 0.0f), Wf);
        y1 = fminf(fmaxf(y1, 0.0f), Hf); y2 = fminf(fmaxf(y2, 0.0f), Hf);
        if ((x2 - x1) >= 0.01f && (y2 - y1) >= 0.01f) {
            int pos = atomicAdd(&g_cnt[b], 1);
            size_t o = (size_t)b * MAXC + pos;
            g_box[o] = make_float4(x1, y1, x2, y2);
            g_s[o]   = sc;
            g_lab[o] = (unsigned char)c;
        }
    }
}

// Phase B: one block per image. 100 sequential greedy-NMS iterations:
// block-wide argmax over K compacted scores (shared memory), then suppression
// restricted to same-class candidates (class-offset trick => cross-class IoU=0).
__global__ void __launch_bounds__(1024, 1)
nms_kernel(float* __restrict__ out,
           const int* __restrict__ ph,
           const int* __restrict__ pw) {
    const int b   = blockIdx.x;
    const int tid = threadIdx.x;
    const int K   = g_cnt[b];

    extern __shared__ unsigned char smraw[];
    float* ss = (float*)smraw;                       // SMEM_CAP floats
    unsigned char* sl = (unsigned char*)(ss + SMEM_CAP);

    __shared__ float red_v[32];
    __shared__ int   red_i[32];
    __shared__ int   selIdx[NDET];
    __shared__ float selSc[NDET];
    __shared__ unsigned char selOk[NDET];
    __shared__ unsigned char selLab[NDET];
    __shared__ float4 sObi;
    __shared__ float  sAi;
    __shared__ int    sSel;
    __shared__ int    sLab;

    const float Hf = load_dim(ph);
    const float Wf = load_dim(pw);
    const float off = fmaxf(Hf, Wf) + 1.0f;

    const bool useSm = (K <= SMEM_CAP);
    const size_t base = (size_t)b * MAXC;
    const float4* BX = g_box + base;
    float* S = useSm ? ss : (g_s + base);

    if (useSm) {
        for (int j = tid; j < K; j += blockDim.x) {
            ss[j] = g_s[base + j];
            sl[j] = g_lab[base + j];
        }
    }
    __syncthreads();

    for (int it = 0; it < NDET; it++) {
        // ---- block argmax over S[0..K) ----
        float bv = -2e9f; int bi = 0;
        for (int j = tid; j < K; j += blockDim.x) {
            float v = S[j];
            if (v > bv) { bv = v; bi = j; }
        }
        #pragma unroll
        for (int o = 16; o; o >>= 1) {
            float ov = __shfl_xor_sync(0xffffffffu, bv, o);
            int   oi = __shfl_xor_sync(0xffffffffu, bi, o);
            if (ov > bv || (ov == bv && oi < bi)) { bv = ov; bi = oi; }
        }
        if ((tid & 31) == 0) { red_v[tid >> 5] = bv; red_i[tid >> 5] = bi; }
        __syncthreads();
        if (tid < 32) {
            int nw = blockDim.x >> 5;
            bv = (tid < nw) ? red_v[tid] : -2e9f;
            bi = (tid < nw) ? red_i[tid] : 0;
            #pragma unroll
            for (int o = 16; o; o >>= 1) {
                float ov = __shfl_xor_sync(0xffffffffu, bv, o);
                int   oi = __shfl_xor_sync(0xffffffffu, bi, o);
                if (ov > bv || (ov == bv && oi < bi)) { bv = ov; bi = oi; }
            }
            if (tid == 0) {
                bool ok = (K > 0) && (bv > -5e8f);
                sSel = bi;
                selIdx[it] = bi;
                selSc[it]  = ok ? bv : 0.0f;
                selOk[it]  = ok ? 1 : 0;
                if (ok) {
                    float4 bx = BX[bi];
                    int L = useSm ? (int)sl[bi] : (int)g_lab[base + bi];
                    float t = (float)L * off;
                    float4 obi = make_float4(bx.x + t, bx.y + t, bx.z + t, bx.w + t);
                    sObi = obi;
                    sAi  = (obi.z - obi.x) * (obi.w - obi.y);
                    sLab = L;
                    selLab[it] = (unsigned char)L;
                } else {
                    sLab = -1;
                    selLab[it] = 0;
                }
            }
        }
        __syncthreads();

        int L = sLab;
        if (L < 0) {
            // nothing left: all remaining iterations are not-ok; fill and exit
            for (int i = it + tid; i < NDET; i += blockDim.x) {
                selOk[i] = 0; selSc[i] = 0.0f; selLab[i] = 0; selIdx[i] = 0;
            }
            break;
        }

        // ---- suppression: same-class candidates only ----
        float4 obi = sObi;
        float ai = sAi;
        for (int j = tid; j < K; j += blockDim.x) {
            int lj = useSm ? (int)sl[j] : (int)g_lab[base + j];
            if (lj != L) continue;
            float4 bx = BX[j];
            float t = (float)lj * off;
            float ox1 = bx.x + t, oy1 = bx.y + t, ox2 = bx.z + t, oy2 = bx.w + t;
            float ix1 = fmaxf(obi.x, ox1), iy1 = fmaxf(obi.y, oy1);
            float ix2 = fminf(obi.z, ox2), iy2 = fminf(obi.w, oy2);
            float inter = fmaxf(ix2 - ix1, 0.0f) * fmaxf(iy2 - iy1, 0.0f);
            float area = (ox2 - ox1) * (oy2 - oy1);
            float iou = inter / fmaxf(ai + area - inter, 1e-9f);
            if (iou > 0.5f) S[j] = NEGV;
        }
        if (tid == 0) S[sSel] = NEGV;
        __syncthreads();
    }
    __syncthreads();

    // ---- outputs: [boxes 8*100*4][scores 8*100][labels 8*100][keep 8*100] ----
    const int BOX0 = 0;
    const int SC0  = B_IMG * NDET * 4;
    const int LB0  = SC0 + B_IMG * NDET;
    const int KP0  = LB0 + B_IMG * NDET;
    for (int i = tid; i < NDET; i += blockDim.x) {
        bool ok = selOk[i] != 0;
        float4 bx = ok ? BX[selIdx[i]] : make_float4(0.f, 0.f, 0.f, 0.f);
        float* ob = out + BOX0 + ((size_t)b * NDET + i) * 4;
        ob[0] = bx.x; ob[1] = bx.y; ob[2] = bx.z; ob[3] = bx.w;
        out[SC0 + b * NDET + i] = selSc[i];
        out[LB0 + b * NDET + i] = ok ? (float)selLab[i] : 0.0f;
        out[KP0 + b * NDET + i] = ok ? 1.0f : 0.0f;
    }
}

extern "C" void kernel_launch(void* const* d_in, const int* in_sizes, int n_in,
                              void* d_out, int out_size) {
    const float* logits = (const float*)d_in[0];
    const float* reg    = (const float*)d_in[1];
    const float* props  = (const float*)d_in[2];
    const int*   ih     = (const int*)d_in[3];
    const int*   iw     = (const int*)d_in[4];
    float* out = (float*)d_out;

    const int smem_bytes = SMEM_CAP * 5;  // 220160 B: scores f32 + labels u8
    cudaFuncSetAttribute(nms_kernel, cudaFuncAttributeMaxDynamicSharedMemorySize,
                         smem_bytes);

    zero_cnt_kernel<<<1, 32>>>();
    // 8*4000 proposals, 1 warp each, 4 warps/block
    phaseA_kernel<<<(B_IMG * NPROP) / 4, 128>>>(logits, reg, props, ih, iw);
    nms_kernel<<<B_IMG, 1024, smem_bytes>>>(out, ih, iw);
}

// round 3
// speedup vs baseline: 1.7938x; 1.7938x over previous
#include <cuda_runtime.h>
#include <cstdint>
#include <math.h>

#define B_IMG 8
#define NPROP 4000
#define NCLS 91
#define NCM1 90
#define CAPC 4000                    // max candidates per (image,class) = NPROP
#define MAXC (NPROP * NCM1)          // 360000 per image upper bound
#define NDET 100
#define NEGV -1e9f
#define SORT_CAP 4096
#define SVCAP 45056

static __device__ float4        g_cbox[B_IMG * NCM1 * CAPC];
static __device__ float         g_cs[B_IMG * NCM1 * CAPC];
static __device__ int           g_ccnt[B_IMG * NCM1];
static __device__ float4        g_svbox[B_IMG * MAXC];
static __device__ float         g_svsc[B_IMG * MAXC];
static __device__ unsigned char g_svlab[B_IMG * MAXC];
static __device__ int           g_svcnt[B_IMG];

__device__ __forceinline__ float load_dim(const int* p) {
    int vi = *p;
    if (vi > 0 && vi < 1000000) return (float)vi;
    return __int_as_float(vi);
}

__global__ void zero_cnt_kernel() {
    int t = threadIdx.x;
    if (t < B_IMG * NCM1) g_ccnt[t] = 0;
    if (t < B_IMG) g_svcnt[t] = 0;
}

// Phase A: one warp per proposal. Softmax over 91 logits, decode+clip+filter
// only passing classes, compact into per-(image,class) buckets.
__global__ void phaseA_kernel(const float* __restrict__ logits,
                              const float* __restrict__ reg,
                              const float* __restrict__ props,
                              const int* __restrict__ ph,
                              const int* __restrict__ pw) {
    const int warpsPerBlock = blockDim.x >> 5;
    const int wid  = threadIdx.x >> 5;
    const int lane = threadIdx.x & 31;
    const int p = blockIdx.x * warpsPerBlock + wid;
    if (p >= B_IMG * NPROP) return;

    const float Wf = load_dim(pw);
    const float Hf = load_dim(ph);
    const float CLIPV = 4.135166556742356f;  // log(1000/16)

    const float* z = logits + (size_t)p * NCLS;
    float v0 = z[lane];
    float v1 = z[lane + 32];
    float v2 = (lane < NCLS - 64) ? z[lane + 64] : -INFINITY;
    float m = fmaxf(fmaxf(v0, v1), v2);
    #pragma unroll
    for (int o = 16; o; o >>= 1) m = fmaxf(m, __shfl_xor_sync(0xffffffffu, m, o));
    float e0 = expf(v0 - m), e1 = expf(v1 - m);
    float e2 = (lane < NCLS - 64) ? expf(v2 - m) : 0.0f;
    float ssum = e0 + e1 + e2;
    #pragma unroll
    for (int o = 16; o; o >>= 1) ssum += __shfl_xor_sync(0xffffffffu, ssum, o);

    float px1 = props[p * 4 + 0], py1 = props[p * 4 + 1];
    float px2 = props[p * 4 + 2], py2 = props[p * 4 + 3];
    float w = px2 - px1, h = py2 - py1;
    float cx = px1 + 0.5f * w, cy = py1 + 0.5f * h;

    const int b = p / NPROP;
    const float* rrow = reg + (size_t)p * (NCLS * 4);
    float es[3] = {e0, e1, e2};

    #pragma unroll
    for (int t = 0; t < 3; t++) {
        int c = lane + 32 * t;
        if (c == 0 || c >= NCLS) continue;
        float sc = es[t] / ssum;
        if (!(sc > 0.05f)) continue;
        float r0 = rrow[c * 4 + 0], r1 = rrow[c * 4 + 1];
        float r2 = rrow[c * 4 + 2], r3 = rrow[c * 4 + 3];
        float dx = r0 / 10.0f, dy = r1 / 10.0f;
        float dw = fminf(r2 / 5.0f, CLIPV);
        float dh = fminf(r3 / 5.0f, CLIPV);
        float pcx = dx * w + cx, pcy = dy * h + cy;
        float pwd = expf(dw) * w, phd = expf(dh) * h;
        float x1 = pcx - 0.5f * pwd, y1 = pcy - 0.5f * phd;
        float x2 = pcx + 0.5f * pwd, y2 = pcy + 0.5f * phd;
        x1 = fminf(fmaxf(x1, 0.0f), Wf); x2 = fminf(fmaxf(x2, 0.0f), Wf);
        y1 = fminf(fmaxf(y1, 0.0f), Hf); y2 = fminf(fmaxf(y2, 0.0f), Hf);
        if ((x2 - x1) >= 0.01f && (y2 - y1) >= 0.01f) {
            int bc = b * NCM1 + (c - 1);
            int pos = atomicAdd(&g_ccnt[bc], 1);
            size_t o = (size_t)bc * CAPC + pos;
            g_cbox[o] = make_float4(x1, y1, x2, y2);
            g_cs[o]   = sc;
        }
    }
}

// Phase B: one block per (image,class). Bitonic sort desc by score, greedy NMS
// with parallel suppression, append survivors to per-image list (one atomic).
__global__ void __launch_bounds__(256, 1)
class_nms_kernel(const int* __restrict__ ph, const int* __restrict__ pw) {
    const int c  = blockIdx.x + 1;
    const int b  = blockIdx.y;
    const int bc = b * NCM1 + (c - 1);
    const int tid = threadIdx.x;
    const int n = g_ccnt[bc];
    if (n == 0) return;

    extern __shared__ unsigned char smraw[];
    float*          skey  = (float*)smraw;                          // SORT_CAP
    int*            sidx  = (int*)(skey + SORT_CAP);                // SORT_CAP
    float4*         sbox  = (float4*)(sidx + SORT_CAP);             // SORT_CAP
    unsigned char*  alive = (unsigned char*)(sbox + SORT_CAP);      // SORT_CAP
    unsigned short* ssurv = (unsigned short*)(alive + SORT_CAP);    // SORT_CAP
    __shared__ int sbase_s;

    int P = 1;
    while (P < n) P <<= 1;   // n <= 4000 -> P <= 4096

    const size_t base = (size_t)bc * CAPC;
    for (int j = tid; j < P; j += 256) {
        skey[j] = (j < n) ? g_cs[base + j] : -INFINITY;
        sidx[j] = j;
    }
    __syncthreads();

    // bitonic sort, descending by score
    for (int k = 2; k <= P; k <<= 1) {
        for (int j2 = k >> 1; j2 > 0; j2 >>= 1) {
            for (int i = tid; i < P; i += 256) {
                int ixj = i ^ j2;
                if (ixj > i) {
                    float a = skey[i], bb = skey[ixj];
                    bool desc = ((i & k) == 0);
                    if (desc ? (a < bb) : (a > bb)) {
                        skey[i] = bb; skey[ixj] = a;
                        int tt = sidx[i]; sidx[i] = sidx[ixj]; sidx[ixj] = tt;
                    }
                }
            }
            __syncthreads();
        }
    }

    // gather boxes into sorted order
    for (int i = tid; i < n; i += 256) {
        sbox[i]  = g_cbox[base + sidx[i]];
        alive[i] = 1;
    }
    __syncthreads();

    const float Hf = load_dim(ph);
    const float Wf = load_dim(pw);
    const float off = fmaxf(Hf, Wf) + 1.0f;
    const float t = (float)c * off;

    int nsurv = 0;
    for (int i = 0; i < n; i++) {
        if (!alive[i]) continue;               // uniform across block
        ssurv[nsurv++] = (unsigned short)i;    // redundant same-value write, ok
        float4 bi = sbox[i];
        float ox1 = bi.x + t, oy1 = bi.y + t, ox2 = bi.z + t, oy2 = bi.w + t;
        float ai = (ox2 - ox1) * (oy2 - oy1);
        for (int j = i + 1 + tid; j < n; j += 256) {
            if (!alive[j]) continue;
            float4 bj = sbox[j];
            float jx1 = bj.x + t, jy1 = bj.y + t, jx2 = bj.z + t, jy2 = bj.w + t;
            float ix1 = fmaxf(ox1, jx1), iy1 = fmaxf(oy1, jy1);
            float ix2 = fminf(ox2, jx2), iy2 = fminf(oy2, jy2);
            float inter = fmaxf(ix2 - ix1, 0.0f) * fmaxf(iy2 - iy1, 0.0f);
            float aj = (jx2 - jx1) * (jy2 - jy1);
            float iou = inter / fmaxf(ai + aj - inter, 1e-9f);
            if (iou > 0.5f) alive[j] = 0;
        }
        __syncthreads();
    }

    if (tid == 0) sbase_s = atomicAdd(&g_svcnt[b], nsurv);
    __syncthreads();
    const size_t so = (size_t)b * MAXC + sbase_s;
    for (int s = tid; s < nsurv; s += 256) {
        int i = ssurv[s];
        g_svbox[so + s] = sbox[i];
        g_svsc[so + s]  = skey[i];
        g_svlab[so + s] = (unsigned char)c;
    }
}

// Phase C: one block per image. Top-100 survivors by descending score
// (100 x argmax-and-remove; survivors need no further suppression).
__global__ void __launch_bounds__(1024, 1)
topk_kernel(float* __restrict__ out) {
    const int b   = blockIdx.x;
    const int tid = threadIdx.x;
    const int n   = g_svcnt[b];

    extern __shared__ float ss[];   // SVCAP floats
    __shared__ float red_v[32];
    __shared__ int   red_i[32];
    __shared__ int   selIdx[NDET];
    __shared__ float selSc[NDET];

    const size_t base = (size_t)b * MAXC;
    const bool useSm = (n <= SVCAP);
    float* S = useSm ? ss : (g_svsc + base);
    if (useSm) {
        for (int j = tid; j < n; j += 1024) ss[j] = g_svsc[base + j];
    }
    __syncthreads();

    const int nsel = (n < NDET) ? n : NDET;
    for (int it = 0; it < nsel; it++) {
        float bv = -2e9f; int bi = 0;
        for (int j = tid; j < n; j += 1024) {
            float v = S[j];
            if (v > bv) { bv = v; bi = j; }
        }
        #pragma unroll
        for (int o = 16; o; o >>= 1) {
            float ov = __shfl_xor_sync(0xffffffffu, bv, o);
            int   oi = __shfl_xor_sync(0xffffffffu, bi, o);
            if (ov > bv || (ov == bv && oi < bi)) { bv = ov; bi = oi; }
        }
        if ((tid & 31) == 0) { red_v[tid >> 5] = bv; red_i[tid >> 5] = bi; }
        __syncthreads();
        if (tid < 32) {
            bv = red_v[tid]; bi = red_i[tid];
            #pragma unroll
            for (int o = 16; o; o >>= 1) {
                float ov = __shfl_xor_sync(0xffffffffu, bv, o);
                int   oi = __shfl_xor_sync(0xffffffffu, bi, o);
                if (ov > bv || (ov == bv && oi < bi)) { bv = ov; bi = oi; }
            }
            if (tid == 0) {
                selIdx[it] = bi;
                selSc[it]  = bv;
                S[bi] = NEGV;   // remove; no suppression needed among survivors
            }
        }
        __syncthreads();
    }

    // outputs: [boxes 8*100*4][scores 8*100][labels 8*100][keep 8*100]
    const int SC0 = B_IMG * NDET * 4;
    const int LB0 = SC0 + B_IMG * NDET;
    const int KP0 = LB0 + B_IMG * NDET;
    for (int i = tid; i < NDET; i += 1024) {
        bool ok = i < nsel;
        float4 bx = ok ? g_svbox[base + selIdx[i]] : make_float4(0.f, 0.f, 0.f, 0.f);
        float* ob = out + ((size_t)b * NDET + i) * 4;
        ob[0] = bx.x; ob[1] = bx.y; ob[2] = bx.z; ob[3] = bx.w;
        out[SC0 + b * NDET + i] = ok ? selSc[i] : 0.0f;
        out[LB0 + b * NDET + i] = ok ? (float)g_svlab[base + selIdx[i]] : 0.0f;
        out[KP0 + b * NDET + i] = ok ? 1.0f : 0.0f;
    }
}

extern "C" void kernel_launch(void* const* d_in, const int* in_sizes, int n_in,
                              void* d_out, int out_size) {
    const float* logits = (const float*)d_in[0];
    const float* reg    = (const float*)d_in[1];
    const float* props  = (const float*)d_in[2];
    const int*   ih     = (const int*)d_in[3];
    const int*   iw     = (const int*)d_in[4];
    float* out = (float*)d_out;

    // class_nms smem: skey 16K + sidx 16K + sbox 64K + alive 4K + ssurv 8K
    const int nms_smem  = SORT_CAP * (4 + 4 + 16 + 1 + 2);   // 110592
    const int topk_smem = SVCAP * 4;                          // 180224
    cudaFuncSetAttribute(class_nms_kernel,
                         cudaFuncAttributeMaxDynamicSharedMemorySize, nms_smem);
    cudaFuncSetAttribute(topk_kernel,
                         cudaFuncAttributeMaxDynamicSharedMemorySize, topk_smem);

    zero_cnt_kernel<<<1, 1024>>>();
    phaseA_kernel<<<(B_IMG * NPROP) / 4, 128>>>(logits, reg, props, ih, iw);
    class_nms_kernel<<<dim3(NCM1, B_IMG), 256, nms_smem>>>(ih, iw);
    topk_kernel<<<B_IMG, 1024, topk_smem>>>(out);
}

// round 4
// speedup vs baseline: 3.2052x; 1.7868x over previous
#include <cuda_runtime.h>
#include <cstdint>
#include <math.h>

#define B_IMG 8
#define NPROP 4000
#define NCLS 91
#define NCM1 90
#define CAPC 4000                    // worst-case candidates per (image,class)
#define NDET 100
#define NEGV -1e9f
#define CAPSM 1024                   // smem fast-path cap for class NMS
#define SV_PER_IMG (NCM1 * NDET)     // 9000: survivors per image (capped)
#define GCAP 1024                    // topk gather capacity
#define HBINS 2048
#define HLO 30720                    // (key>>15) offset; covers scores >~0.0078

static __device__ float4        g_cbox[B_IMG * NCM1 * CAPC];
static __device__ float         g_cs[B_IMG * NCM1 * CAPC];
static __device__ int           g_ccnt[B_IMG * NCM1];        // zero-init, self-reset
static __device__ float4        g_svbox[B_IMG * SV_PER_IMG];
static __device__ float         g_svsc[B_IMG * SV_PER_IMG];
static __device__ unsigned char g_svlab[B_IMG * SV_PER_IMG];
static __device__ int           g_svcnt[B_IMG];              // zero-init, self-reset

__device__ __forceinline__ float load_dim(const int* p) {
    int vi = *p;
    if (vi > 0 && vi < 1000000) return (float)vi;
    return __int_as_float(vi);
}

// ---------------------------------------------------------------------------
// Phase A: one warp per proposal. Softmax over 91 logits, decode+clip+filter
// passing classes, compact into per-(image,class) buckets.
// ---------------------------------------------------------------------------
__global__ void phaseA_kernel(const float* __restrict__ logits,
                              const float* __restrict__ reg,
                              const float* __restrict__ props,
                              const int* __restrict__ ph,
                              const int* __restrict__ pw) {
    const int warpsPerBlock = blockDim.x >> 5;
    const int wid  = threadIdx.x >> 5;
    const int lane = threadIdx.x & 31;
    const int p = blockIdx.x * warpsPerBlock + wid;
    if (p >= B_IMG * NPROP) return;

    const float Wf = load_dim(pw);
    const float Hf = load_dim(ph);
    const float CLIPV = 4.135166556742356f;  // log(1000/16)

    const float* z = logits + (size_t)p * NCLS;
    float v0 = z[lane];
    float v1 = z[lane + 32];
    float v2 = (lane < NCLS - 64) ? z[lane + 64] : -INFINITY;
    float m = fmaxf(fmaxf(v0, v1), v2);
    #pragma unroll
    for (int o = 16; o; o >>= 1) m = fmaxf(m, __shfl_xor_sync(0xffffffffu, m, o));
    float e0 = expf(v0 - m), e1 = expf(v1 - m);
    float e2 = (lane < NCLS - 64) ? expf(v2 - m) : 0.0f;
    float ssum = e0 + e1 + e2;
    #pragma unroll
    for (int o = 16; o; o >>= 1) ssum += __shfl_xor_sync(0xffffffffu, ssum, o);

    float px1 = props[p * 4 + 0], py1 = props[p * 4 + 1];
    float px2 = props[p * 4 + 2], py2 = props[p * 4 + 3];
    float w = px2 - px1, h = py2 - py1;
    float cx = px1 + 0.5f * w, cy = py1 + 0.5f * h;

    const int b = p / NPROP;
    const float* rrow = reg + (size_t)p * (NCLS * 4);
    float es[3] = {e0, e1, e2};

    #pragma unroll
    for (int t = 0; t < 3; t++) {
        int c = lane + 32 * t;
        if (c == 0 || c >= NCLS) continue;
        float sc = es[t] / ssum;
        if (!(sc > 0.05f)) continue;
        float r0 = rrow[c * 4 + 0], r1 = rrow[c * 4 + 1];
        float r2 = rrow[c * 4 + 2], r3 = rrow[c * 4 + 3];
        float dx = r0 / 10.0f, dy = r1 / 10.0f;
        float dw = fminf(r2 / 5.0f, CLIPV);
        float dh = fminf(r3 / 5.0f, CLIPV);
        float pcx = dx * w + cx, pcy = dy * h + cy;
        float pwd = expf(dw) * w, phd = expf(dh) * h;
        float x1 = pcx - 0.5f * pwd, y1 = pcy - 0.5f * phd;
        float x2 = pcx + 0.5f * pwd, y2 = pcy + 0.5f * phd;
        x1 = fminf(fmaxf(x1, 0.0f), Wf); x2 = fminf(fmaxf(x2, 0.0f), Wf);
        y1 = fminf(fmaxf(y1, 0.0f), Hf); y2 = fminf(fmaxf(y2, 0.0f), Hf);
        if ((x2 - x1) >= 0.01f && (y2 - y1) >= 0.01f) {
            int bc = b * NCM1 + (c - 1);
            int pos = atomicAdd(&g_ccnt[bc], 1);
            size_t o = (size_t)bc * CAPC + pos;
            g_cbox[o] = make_float4(x1, y1, x2, y2);
            g_cs[o]   = sc;
        }
    }
}

// ---------------------------------------------------------------------------
// Phase B: one block per (image,class). Sort desc, greedy NMS (warp 0,
// __syncwarp only), cap survivors at NDET, append to per-image list.
// ---------------------------------------------------------------------------
__global__ void __launch_bounds__(256)
class_nms_kernel(const int* __restrict__ ph, const int* __restrict__ pw) {
    const int c  = blockIdx.x + 1;
    const int b  = blockIdx.y;
    const int bc = b * NCM1 + (c - 1);
    const int tid = threadIdx.x;
    const int n = g_ccnt[bc];
    if (n == 0) return;

    __shared__ float          skey[CAPSM];
    __shared__ unsigned short sidx[CAPSM];
    __shared__ float4         sbox[CAPSM];
    __shared__ unsigned char  alive[CAPSM];
    __shared__ unsigned short surv[NDET];
    __shared__ float          survsc[NDET];
    __shared__ int            nsurv_s, sbase_s;
    __shared__ float          red_v[8];
    __shared__ int            red_i[8];
    __shared__ int            stop_s, seli_s;
    __shared__ float4         selbox_s;

    const float Hf = load_dim(ph);
    const float Wf = load_dim(pw);
    const float off = fmaxf(Hf, Wf) + 1.0f;
    const float t = (float)c * off;
    const size_t base = (size_t)bc * CAPC;

    if (n <= CAPSM) {
        // ------- smem fast path -------
        int P = 1;
        while (P < n) P <<= 1;
        for (int j = tid; j < P; j += 256) {
            skey[j] = (j < n) ? g_cs[base + j] : -INFINITY;
            sidx[j] = (unsigned short)j;
        }
        __syncthreads();
        // bitonic sort descending by score
        for (int k = 2; k <= P; k <<= 1) {
            for (int j2 = k >> 1; j2 > 0; j2 >>= 1) {
                for (int i = tid; i < P; i += 256) {
                    int ixj = i ^ j2;
                    if (ixj > i) {
                        float a = skey[i], bb = skey[ixj];
                        bool desc = ((i & k) == 0);
                        if (desc ? (a < bb) : (a > bb)) {
                            skey[i] = bb; skey[ixj] = a;
                            unsigned short tt = sidx[i]; sidx[i] = sidx[ixj]; sidx[ixj] = tt;
                        }
                    }
                }
                __syncthreads();
            }
        }
        for (int i = tid; i < n; i += 256) {
            sbox[i]  = g_cbox[base + sidx[i]];
            alive[i] = 1;
        }
        __syncthreads();

        // greedy NMS with warp 0 only; stop after NDET survivors
        if (tid < 32) {
            int ns = 0;
            for (int i = 0; i < n && ns < NDET; i++) {
                if (alive[i] == 0) continue;
                if (tid == 0) { surv[ns] = (unsigned short)i; survsc[ns] = skey[i]; }
                ns++;
                float4 bi = sbox[i];
                float ox1 = bi.x + t, oy1 = bi.y + t, ox2 = bi.z + t, oy2 = bi.w + t;
                float ai = (ox2 - ox1) * (oy2 - oy1);
                for (int j = i + 1 + tid; j < n; j += 32) {
                    if (!alive[j]) continue;
                    float4 bj = sbox[j];
                    float jx1 = bj.x + t, jy1 = bj.y + t, jx2 = bj.z + t, jy2 = bj.w + t;
                    float ix1 = fmaxf(ox1, jx1), iy1 = fmaxf(oy1, jy1);
                    float ix2 = fminf(ox2, jx2), iy2 = fminf(oy2, jy2);
                    float inter = fmaxf(ix2 - ix1, 0.0f) * fmaxf(iy2 - iy1, 0.0f);
                    float aj = (jx2 - jx1) * (jy2 - jy1);
                    float iou = inter / fmaxf(ai + aj - inter, 1e-9f);
                    if (iou > 0.5f) alive[j] = 0;
                }
                __syncwarp();
            }
            if (tid == 0) nsurv_s = ns;
        }
        __syncthreads();

        if (tid == 0) sbase_s = atomicAdd(&g_svcnt[b], nsurv_s);
        __syncthreads();
        const int so = b * SV_PER_IMG + sbase_s;
        for (int s = tid; s < nsurv_s; s += 256) {
            int i = surv[s];
            g_svbox[so + s] = sbox[i];
            g_svsc[so + s]  = skey[i];
            g_svlab[so + s] = (unsigned char)c;
        }
    } else {
        // ------- global fallback (n > 1024; essentially never) -------
        int ns = 0;
        for (int it = 0; it < NDET; it++) {
            float bv = -2e9f; int bi = 0;
            for (int j = tid; j < n; j += 256) {
                float v = g_cs[base + j];
                if (v > bv) { bv = v; bi = j; }
            }
            #pragma unroll
            for (int o = 16; o; o >>= 1) {
                float ov = __shfl_xor_sync(0xffffffffu, bv, o);
                int   oi = __shfl_xor_sync(0xffffffffu, bi, o);
                if (ov > bv || (ov == bv && oi < bi)) { bv = ov; bi = oi; }
            }
            if ((tid & 31) == 0) { red_v[tid >> 5] = bv; red_i[tid >> 5] = bi; }
            __syncthreads();
            if (tid == 0) {
                for (int wv = 1; wv < 8; wv++) {
                    if (red_v[wv] > red_v[0] ||
                        (red_v[wv] == red_v[0] && red_i[wv] < red_i[0])) {
                        red_v[0] = red_v[wv]; red_i[0] = red_i[wv];
                    }
                }
                if (red_v[0] < -5e8f) { stop_s = 1; }
                else {
                    stop_s = 0; seli_s = red_i[0];
                    selbox_s = g_cbox[base + red_i[0]];
                    surv[ns] = (unsigned short)0;  // unused in this path
                    survsc[ns] = red_v[0];
                }
            }
            __syncthreads();
            if (stop_s) break;
            float4 bx = selbox_s;
            float ox1 = bx.x + t, oy1 = bx.y + t, ox2 = bx.z + t, oy2 = bx.w + t;
            float ai = (ox2 - ox1) * (oy2 - oy1);
            for (int j = tid; j < n; j += 256) {
                float v = g_cs[base + j];
                if (v < -5e8f) continue;
                float4 bj = g_cbox[base + j];
                float jx1 = bj.x + t, jy1 = bj.y + t, jx2 = bj.z + t, jy2 = bj.w + t;
                float ix1 = fmaxf(ox1, jx1), iy1 = fmaxf(oy1, jy1);
                float ix2 = fminf(ox2, jx2), iy2 = fminf(oy2, jy2);
                float inter = fmaxf(ix2 - ix1, 0.0f) * fmaxf(iy2 - iy1, 0.0f);
                float aj = (jx2 - jx1) * (jy2 - jy1);
                float iou = inter / fmaxf(ai + aj - inter, 1e-9f);
                if (iou > 0.5f) g_cs[base + j] = NEGV;
            }
            __syncthreads();
            if (tid == 0) { g_cs[base + seli_s] = NEGV; seli_s = (ns << 16) | seli_s; }
            __syncthreads();
            if (tid == 0) surv[ns] = (unsigned short)(seli_s & 0xFFFF);
            ns++;
            __syncthreads();
        }
        __shared__ int sb2;
        if (tid == 0) sb2 = atomicAdd(&g_svcnt[b], ns);
        __syncthreads();
        const int so = b * SV_PER_IMG + sb2;
        for (int s = tid; s < ns; s += 256) {
            g_svbox[so + s] = g_cbox[base + surv[s]];
            g_svsc[so + s]  = survsc[s];
            g_svlab[so + s] = (unsigned char)c;
        }
    }
    __syncthreads();
    if (tid == 0) g_ccnt[bc] = 0;   // self-reset for next replay
}

// ---------------------------------------------------------------------------
// Phase C: one block per image. Radix-select top-100 of n<=9000 survivors:
// histogram -> suffix sum -> pivot -> gather <=1024 -> small bitonic sort.
// ---------------------------------------------------------------------------
__global__ void __launch_bounds__(1024)
topk_kernel(float* __restrict__ out) {
    const int b   = blockIdx.x;
    const int tid = threadIdx.x;
    const int n   = g_svcnt[b];
    const int base = b * SV_PER_IMG;
    const int nsel = (n < NDET) ? n : NDET;

    __shared__ int hist[HBINS];
    __shared__ unsigned long long keys[GCAP];
    __shared__ int gcnt_s, pb_s;

    for (int i = tid; i < HBINS; i += 1024) hist[i] = 0;
    if (tid == 0) { gcnt_s = 0; pb_s = 0; }
    __syncthreads();

    for (int j = tid; j < n; j += 1024) {
        unsigned k = __float_as_uint(g_svsc[base + j]);
        int bkt = (int)(k >> 15) - HLO;
        bkt = max(0, min(HBINS - 1, bkt));
        atomicAdd(&hist[bkt], 1);
    }
    __syncthreads();

    // inclusive suffix sum (Hillis-Steele), 2 elems/thread
    for (int d = 1; d < HBINS; d <<= 1) {
        int i0 = tid, i1 = tid + 1024;
        int v0 = hist[i0] + ((i0 + d < HBINS) ? hist[i0 + d] : 0);
        int v1 = hist[i1] + ((i1 + d < HBINS) ? hist[i1 + d] : 0);
        __syncthreads();
        hist[i0] = v0; hist[i1] = v1;
        __syncthreads();
    }

    // pivot bucket: largest i with suffix_count >= nsel
    if (nsel > 0) {
        for (int i = tid; i < HBINS; i += 1024) {
            int s = hist[i];
            int sn = (i + 1 < HBINS) ? hist[i + 1] : 0;
            if (s >= nsel && sn < nsel) pb_s = i;
        }
    }
    __syncthreads();
    const int pb = pb_s;
    const int m  = (nsel > 0) ? hist[pb] : 0;

    if (m <= GCAP) {
        // gather all candidates in buckets >= pivot
        for (int j = tid; j < n; j += 1024) {
            unsigned k = __float_as_uint(g_svsc[base + j]);
            int bkt = (int)(k >> 15) - HLO;
            bkt = max(0, min(HBINS - 1, bkt));
            if (bkt >= pb) {
                int slot = atomicAdd(&gcnt_s, 1);
                keys[slot] = ((unsigned long long)k << 32) | (unsigned)(~j);
            }
        }
        __syncthreads();
        int GP = 1;
        while (GP < m) GP <<= 1;
        for (int i = m + tid; i < GP; i += 1024) keys[i] = 0ull;
        __syncthreads();
        // bitonic sort descending on composite key (score desc, idx asc)
        for (int k2 = 2; k2 <= GP; k2 <<= 1) {
            for (int j2 = k2 >> 1; j2 > 0; j2 >>= 1) {
                for (int i = tid; i < GP; i += 1024) {
                    int ixj = i ^ j2;
                    if (ixj > i) {
                        unsigned long long a = keys[i], bb = keys[ixj];
                        bool desc = ((i & k2) == 0);
                        if (desc ? (a < bb) : (a > bb)) { keys[i] = bb; keys[ixj] = a; }
                    }
                }
                __syncthreads();
            }
        }
    } else {
        // fallback: destructive argmax loop (pathological tie pile-up only)
        __shared__ float red_v[32];
        __shared__ int   red_i[32];
        for (int it = 0; it < nsel; it++) {
            float bv = -2e9f; int bi = 0;
            for (int j = tid; j < n; j += 1024) {
                float v = g_svsc[base + j];
                if (v > bv) { bv = v; bi = j; }
            }
            #pragma unroll
            for (int o = 16; o; o >>= 1) {
                float ov = __shfl_xor_sync(0xffffffffu, bv, o);
                int   oi = __shfl_xor_sync(0xffffffffu, bi, o);
                if (ov > bv || (ov == bv && oi < bi)) { bv = ov; bi = oi; }
            }
            if ((tid & 31) == 0) { red_v[tid >> 5] = bv; red_i[tid >> 5] = bi; }
            __syncthreads();
            if (tid == 0) {
                for (int wv = 1; wv < 32; wv++)
                    if (red_v[wv] > red_v[0] ||
                        (red_v[wv] == red_v[0] && red_i[wv] < red_i[0])) {
                        red_v[0] = red_v[wv]; red_i[0] = red_i[wv];
                    }
                int bsel = red_i[0];
                keys[it] = ((unsigned long long)__float_as_uint(red_v[0]) << 32)
                         | (unsigned)(~bsel);
                g_svsc[base + bsel] = NEGV;
            }
            __syncthreads();
        }
    }

    // emit: [boxes 8*100*4][scores 8*100][labels 8*100][keep 8*100]
    const int SC0 = B_IMG * NDET * 4;
    const int LB0 = SC0 + B_IMG * NDET;
    const int KP0 = LB0 + B_IMG * NDET;
    for (int i = tid; i < NDET; i += 1024) {
        float4 bx = make_float4(0.f, 0.f, 0.f, 0.f);
        float sc = 0.0f, lb = 0.0f, kp = 0.0f;
        if (i < nsel) {
            unsigned long long kk = keys[i];
            int j = (int)(~(unsigned)kk);
            bx = g_svbox[base + j];
            sc = __uint_as_float((unsigned)(kk >> 32));
            lb = (float)g_svlab[base + j];
            kp = 1.0f;
        }
        float* ob = out + ((size_t)b * NDET + i) * 4;
        ob[0] = bx.x; ob[1] = bx.y; ob[2] = bx.z; ob[3] = bx.w;
        out[SC0 + b * NDET + i] = sc;
        out[LB0 + b * NDET + i] = lb;
        out[KP0 + b * NDET + i] = kp;
    }
    if (tid == 0) g_svcnt[b] = 0;   // self-reset for next replay
}

extern "C" void kernel_launch(void* const* d_in, const int* in_sizes, int n_in,
                              void* d_out, int out_size) {
    const float* logits = (const float*)d_in[0];
    const float* reg    = (const float*)d_in[1];
    const float* props  = (const float*)d_in[2];
    const int*   ih     = (const int*)d_in[3];
    const int*   iw     = (const int*)d_in[4];
    float* out = (float*)d_out;

    phaseA_kernel<<<(B_IMG * NPROP) / 4, 128>>>(logits, reg, props, ih, iw);
    class_nms_kernel<<<dim3(NCM1, B_IMG), 256>>>(ih, iw);
    topk_kernel<<<B_IMG, 1024>>>(out);
}

// round 5
// speedup vs baseline: 5.5759x; 1.7396x over previous
#include <cuda_runtime.h>
#include <cstdint>
#include <math.h>

#define B_IMG 8
#define NPROP 4000
#define NCLS 91
#define NCM1 90
#define CAPC 4000                    // worst-case candidates per (image,class)
#define NDET 100
#define NEGV -1e9f
#define CAPSM 512                    // smem mask-path cap for class NMS
#define NWMAX 8                      // CAPSM/64 mask words per row
#define SV_PER_IMG (NCM1 * NDET)     // 9000 survivors per image (capped)
#define GCAP 1024                    // topk gather capacity
#define HBINS 2048
#define HLO 30720                    // (key>>15) offset; covers scores >~0.0078

static __device__ float4        g_cbox[B_IMG * NCM1 * CAPC];
static __device__ float         g_cs[B_IMG * NCM1 * CAPC];
static __device__ int           g_ccnt[B_IMG * NCM1];        // zero-init, self-reset
static __device__ float4        g_svbox[B_IMG * SV_PER_IMG];
static __device__ float         g_svsc[B_IMG * SV_PER_IMG];
static __device__ unsigned char g_svlab[B_IMG * SV_PER_IMG];
static __device__ int           g_svcnt[B_IMG];              // zero-init, self-reset

__device__ __forceinline__ float load_dim(const int* p) {
    int vi = *p;
    if (vi > 0 && vi < 1000000) return (float)vi;
    return __int_as_float(vi);
}

// ---------------------------------------------------------------------------
// Phase A: one warp per proposal. Softmax over 91 logits; threshold via
// multiply (e > 0.05*ssum); decode+divide only for passers; compact into
// per-(image,class) buckets.
// ---------------------------------------------------------------------------
__global__ void phaseA_kernel(const float* __restrict__ logits,
                              const float* __restrict__ reg,
                              const float* __restrict__ props,
                              const int* __restrict__ ph,
                              const int* __restrict__ pw) {
    const int warpsPerBlock = blockDim.x >> 5;
    const int wid  = threadIdx.x >> 5;
    const int lane = threadIdx.x & 31;
    const int p = blockIdx.x * warpsPerBlock + wid;
    if (p >= B_IMG * NPROP) return;

    const float Wf = load_dim(pw);
    const float Hf = load_dim(ph);
    const float CLIPV = 4.135166556742356f;  // log(1000/16)

    const float* z = logits + (size_t)p * NCLS;
    float v0 = z[lane];
    float v1 = z[lane + 32];
    float v2 = (lane < NCLS - 64) ? z[lane + 64] : -INFINITY;
    float m = fmaxf(fmaxf(v0, v1), v2);
    #pragma unroll
    for (int o = 16; o; o >>= 1) m = fmaxf(m, __shfl_xor_sync(0xffffffffu, m, o));
    float e0 = expf(v0 - m), e1 = expf(v1 - m);
    float e2 = (lane < NCLS - 64) ? expf(v2 - m) : 0.0f;
    float ssum = e0 + e1 + e2;
    #pragma unroll
    for (int o = 16; o; o >>= 1) ssum += __shfl_xor_sync(0xffffffffu, ssum, o);
    const float thr = 0.05f * ssum;

    float px1 = props[p * 4 + 0], py1 = props[p * 4 + 1];
    float px2 = props[p * 4 + 2], py2 = props[p * 4 + 3];
    float w = px2 - px1, h = py2 - py1;
    float cx = px1 + 0.5f * w, cy = py1 + 0.5f * h;

    const int b = p / NPROP;
    const float4* rrow = (const float4*)(reg + (size_t)p * (NCLS * 4));
    float es[3] = {e0, e1, e2};

    #pragma unroll
    for (int t = 0; t < 3; t++) {
        int c = lane + 32 * t;
        if (c == 0 || c >= NCLS) continue;
        float e = es[t];
        if (!(e > thr)) continue;                 // rare path below
        float sc = e / ssum;                      // exact score for passers only
        float4 r = rrow[c];
        float dx = r.x / 10.0f, dy = r.y / 10.0f;
        float dw = fminf(r.z / 5.0f, CLIPV);
        float dh = fminf(r.w / 5.0f, CLIPV);
        float pcx = dx * w + cx, pcy = dy * h + cy;
        float pwd = expf(dw) * w, phd = expf(dh) * h;
        float x1 = pcx - 0.5f * pwd, y1 = pcy - 0.5f * phd;
        float x2 = pcx + 0.5f * pwd, y2 = pcy + 0.5f * phd;
        x1 = fminf(fmaxf(x1, 0.0f), Wf); x2 = fminf(fmaxf(x2, 0.0f), Wf);
        y1 = fminf(fmaxf(y1, 0.0f), Hf); y2 = fminf(fmaxf(y2, 0.0f), Hf);
        if ((x2 - x1) >= 0.01f && (y2 - y1) >= 0.01f) {
            int bc = b * NCM1 + (c - 1);
            int pos = atomicAdd(&g_ccnt[bc], 1);
            size_t o = (size_t)bc * CAPC + pos;
            g_cbox[o] = make_float4(x1, y1, x2, y2);
            g_cs[o]   = sc;
        }
    }
}

// ---------------------------------------------------------------------------
// Phase B: one block per (image,class). Bitonic sort (u64 composite keys),
// parallel O(n^2/2) suppression bitmask (no divisions), register-resident
// greedy bit-scan by thread 0, cap survivors at NDET, append per image.
// ---------------------------------------------------------------------------
__global__ void __launch_bounds__(256)
class_nms_kernel(const int* __restrict__ ph, const int* __restrict__ pw) {
    const int c  = blockIdx.x + 1;
    const int b  = blockIdx.y;
    const int bc = b * NCM1 + (c - 1);
    const int tid = threadIdx.x;
    const int n = g_ccnt[bc];
    if (n == 0) return;

    __shared__ unsigned long long skey[CAPSM];           // 4KB composite keys
    __shared__ float4             sbox[CAPSM];           // 8KB
    __shared__ unsigned long long mask[CAPSM * NWMAX];   // 32KB suppression bits
    __shared__ unsigned short     surv[NDET];
    __shared__ float              survsc[NDET];
    __shared__ int                nsurv_s, sbase_s;
    __shared__ float              red_v[8];
    __shared__ int                red_i[8];
    __shared__ int                stop_s, seli_s;
    __shared__ float4             selbox_s;

    const float Hf = load_dim(ph);
    const float Wf = load_dim(pw);
    const float off = fmaxf(Hf, Wf) + 1.0f;
    const float t = (float)c * off;
    const size_t base = (size_t)bc * CAPC;

    if (n <= CAPSM) {
        // ---------------- smem mask fast path ----------------
        int P = 1;
        while (P < n) P <<= 1;
        for (int j = tid; j < P; j += 256) {
            skey[j] = (j < n)
                ? ((unsigned long long)__float_as_uint(g_cs[base + j]) << 32) | (unsigned)j
                : 0ull;
        }
        __syncthreads();
        // bitonic sort, descending by composite key (score desc, idx desc on ties)
        for (int k = 2; k <= P; k <<= 1) {
            for (int j2 = k >> 1; j2 > 0; j2 >>= 1) {
                for (int i = tid; i < P; i += 256) {
                    int ixj = i ^ j2;
                    if (ixj > i) {
                        unsigned long long a = skey[i], bb = skey[ixj];
                        bool desc = ((i & k) == 0);
                        if (desc ? (a < bb) : (a > bb)) { skey[i] = bb; skey[ixj] = a; }
                    }
                }
                __syncthreads();
            }
        }
        for (int i = tid; i < n; i += 256)
            sbox[i] = g_cbox[base + (unsigned)(skey[i] & 0xffffffffu)];
        __syncthreads();

        // suppression bitmask: mask[i][w] bit j set iff j>i and IoU(i,j) > 0.5.
        // IoU > 0.5  <=>  inter > 0.5*(ai+aj-inter)   (union >= 1e-4 >> 1e-9 clamp)
        const int NW = (n + 63) >> 6;
        for (int idx = tid; idx < n * NW; idx += 256) {
            int i = idx / NW, w = idx - i * NW;
            unsigned long long bits = 0ull;
            int j0 = w << 6;
            int jend = min(n, j0 + 64);
            int jbeg = max(j0, i + 1);
            if (jbeg < jend) {
                float4 bi = sbox[i];
                float ox1 = bi.x, oy1 = bi.y, ox2 = bi.z, oy2 = bi.w;
                float ai = (ox2 - ox1) * (oy2 - oy1);
                for (int j = jbeg; j < jend; j++) {
                    float4 bj = sbox[j];
                    float ix1 = fmaxf(ox1, bj.x), iy1 = fmaxf(oy1, bj.y);
                    float ix2 = fminf(ox2, bj.z), iy2 = fminf(oy2, bj.w);
                    float inter = fmaxf(ix2 - ix1, 0.0f) * fmaxf(iy2 - iy1, 0.0f);
                    float aj = (bj.z - bj.x) * (bj.w - bj.y);
                    if (inter > 0.5f * (ai + aj - inter))
                        bits |= 1ull << (j - j0);
                }
            }
            mask[i * NWMAX + w] = bits;
        }
        __syncthreads();

        // greedy scan, dead-set in registers
        if (tid == 0) {
            unsigned long long dead[NWMAX];
            #pragma unroll
            for (int w = 0; w < NWMAX; w++) dead[w] = 0ull;
            int ns = 0;
            for (int i = 0; i < n && ns < NDET; i++) {
                if ((dead[i >> 6] >> (i & 63)) & 1ull) continue;
                surv[ns] = (unsigned short)i;
                survsc[ns] = __uint_as_float((unsigned)(skey[i] >> 32));
                ns++;
                for (int w = i >> 6; w < NW; w++) dead[w] |= mask[i * NWMAX + w];
            }
            nsurv_s = ns;
            sbase_s = atomicAdd(&g_svcnt[b], ns);
        }
        __syncthreads();
        const int so = b * SV_PER_IMG + sbase_s;
        for (int s = tid; s < nsurv_s; s += 256) {
            int i = surv[s];
            g_svbox[so + s] = sbox[i];
            g_svsc[so + s]  = survsc[s];
            g_svlab[so + s] = (unsigned char)c;
        }
    } else {
        // ---------------- global fallback (n > 512; essentially never) ------
        __shared__ float gsc[NDET];
        int ns = 0;
        for (int it = 0; it < NDET; it++) {
            float bv = -2e9f; int bi = 0;
            for (int j = tid; j < n; j += 256) {
                float v = g_cs[base + j];
                if (v > bv) { bv = v; bi = j; }
            }
            #pragma unroll
            for (int o = 16; o; o >>= 1) {
                float ov = __shfl_xor_sync(0xffffffffu, bv, o);
                int   oi = __shfl_xor_sync(0xffffffffu, bi, o);
                if (ov > bv || (ov == bv && oi < bi)) { bv = ov; bi = oi; }
            }
            if ((tid & 31) == 0) { red_v[tid >> 5] = bv; red_i[tid >> 5] = bi; }
            __syncthreads();
            if (tid == 0) {
                for (int wv = 1; wv < 8; wv++)
                    if (red_v[wv] > red_v[0] ||
                        (red_v[wv] == red_v[0] && red_i[wv] < red_i[0])) {
                        red_v[0] = red_v[wv]; red_i[0] = red_i[wv];
                    }
                if (red_v[0] < -5e8f) stop_s = 1;
                else {
                    stop_s = 0; seli_s = red_i[0];
                    selbox_s = g_cbox[base + red_i[0]];
                    gsc[ns] = red_v[0];
                    surv[ns] = 0;
                }
            }
            __syncthreads();
            if (stop_s) break;
            float4 bx = selbox_s;
            float ox1 = bx.x + t, oy1 = bx.y + t, ox2 = bx.z + t, oy2 = bx.w + t;
            float ai = (ox2 - ox1) * (oy2 - oy1);
            for (int j = tid; j < n; j += 256) {
                float v = g_cs[base + j];
                if (v < -5e8f) continue;
                float4 bj = g_cbox[base + j];
                float jx1 = bj.x + t, jy1 = bj.y + t, jx2 = bj.z + t, jy2 = bj.w + t;
                float ix1 = fmaxf(ox1, jx1), iy1 = fmaxf(oy1, jy1);
                float ix2 = fminf(ox2, jx2), iy2 = fminf(oy2, jy2);
                float inter = fmaxf(ix2 - ix1, 0.0f) * fmaxf(iy2 - iy1, 0.0f);
                float aj = (jx2 - jx1) * (jy2 - jy1);
                if (inter > 0.5f * (ai + aj - inter)) g_cs[base + j] = NEGV;
            }
            __syncthreads();
            if (tid == 0) {
                g_cs[base + seli_s] = NEGV;
                surv[ns] = (unsigned short)(seli_s & 0xFFFF);
                // store full index in red_i[0] reused? indices can exceed 65535:
                red_i[1] = seli_s;
            }
            __syncthreads();
            if (tid == 0) {
                g_svbox[b * SV_PER_IMG] = g_svbox[b * SV_PER_IMG]; // no-op keep
            }
            // write survivor immediately (index may exceed 16 bits)
            if (tid == 0) {
                int slot = atomicAdd(&g_svcnt[b], 1);
                g_svbox[b * SV_PER_IMG + slot] = g_cbox[base + red_i[1]];
                g_svsc[b * SV_PER_IMG + slot]  = gsc[ns];
                g_svlab[b * SV_PER_IMG + slot] = (unsigned char)c;
            }
            ns++;
            __syncthreads();
        }
    }
    __syncthreads();
    if (tid == 0) g_ccnt[bc] = 0;   // self-reset for next graph replay
}

// ---------------------------------------------------------------------------
// Phase C: one block per image. Radix-select top-100 of n<=9000 survivors:
// histogram -> suffix sum -> pivot -> gather <=1024 -> small bitonic sort.
// ---------------------------------------------------------------------------
__global__ void __launch_bounds__(1024)
topk_kernel(float* __restrict__ out) {
    const int b   = blockIdx.x;
    const int tid = threadIdx.x;
    const int n   = g_svcnt[b];
    const int base = b * SV_PER_IMG;
    const int nsel = (n < NDET) ? n : NDET;

    __shared__ int hist[HBINS];
    __shared__ unsigned long long keys[GCAP];
    __shared__ int gcnt_s, pb_s;

    for (int i = tid; i < HBINS; i += 1024) hist[i] = 0;
    if (tid == 0) { gcnt_s = 0; pb_s = 0; }
    __syncthreads();

    for (int j = tid; j < n; j += 1024) {
        unsigned k = __float_as_uint(g_svsc[base + j]);
        int bkt = (int)(k >> 15) - HLO;
        bkt = max(0, min(HBINS - 1, bkt));
        atomicAdd(&hist[bkt], 1);
    }
    __syncthreads();

    // inclusive suffix sum (Hillis-Steele), 2 elems/thread
    for (int d = 1; d < HBINS; d <<= 1) {
        int i0 = tid, i1 = tid + 1024;
        int v0 = hist[i0] + ((i0 + d < HBINS) ? hist[i0 + d] : 0);
        int v1 = hist[i1] + ((i1 + d < HBINS) ? hist[i1 + d] : 0);
        __syncthreads();
        hist[i0] = v0; hist[i1] = v1;
        __syncthreads();
    }

    if (nsel > 0) {
        for (int i = tid; i < HBINS; i += 1024) {
            int s = hist[i];
            int sn = (i + 1 < HBINS) ? hist[i + 1] : 0;
            if (s >= nsel && sn < nsel) pb_s = i;
        }
    }
    __syncthreads();
    const int pb = pb_s;
    const int m  = (nsel > 0) ? hist[pb] : 0;

    if (m <= GCAP) {
        for (int j = tid; j < n; j += 1024) {
            unsigned k = __float_as_uint(g_svsc[base + j]);
            int bkt = (int)(k >> 15) - HLO;
            bkt = max(0, min(HBINS - 1, bkt));
            if (bkt >= pb) {
                int slot = atomicAdd(&gcnt_s, 1);
                keys[slot] = ((unsigned long long)k << 32) | (unsigned)(~j);
            }
        }
        __syncthreads();
        int GP = 1;
        while (GP < m) GP <<= 1;
        for (int i = m + tid; i < GP; i += 1024) keys[i] = 0ull;
        __syncthreads();
        for (int k2 = 2; k2 <= GP; k2 <<= 1) {
            for (int j2 = k2 >> 1; j2 > 0; j2 >>= 1) {
                for (int i = tid; i < GP; i += 1024) {
                    int ixj = i ^ j2;
                    if (ixj > i) {
                        unsigned long long a = keys[i], bb = keys[ixj];
                        bool desc = ((i & k2) == 0);
                        if (desc ? (a < bb) : (a > bb)) { keys[i] = bb; keys[ixj] = a; }
                    }
                }
                __syncthreads();
            }
        }
    } else {
        // fallback: destructive argmax loop (pathological tie pile-up only)
        __shared__ float red_v[32];
        __shared__ int   red_i[32];
        for (int it = 0; it < nsel; it++) {
            float bv = -2e9f; int bi = 0;
            for (int j = tid; j < n; j += 1024) {
                float v = g_svsc[base + j];
                if (v > bv) { bv = v; bi = j; }
            }
            #pragma unroll
            for (int o = 16; o; o >>= 1) {
                float ov = __shfl_xor_sync(0xffffffffu, bv, o);
                int   oi = __shfl_xor_sync(0xffffffffu, bi, o);
                if (ov > bv || (ov == bv && oi < bi)) { bv = ov; bi = oi; }
            }
            if ((tid & 31) == 0) { red_v[tid >> 5] = bv; red_i[tid >> 5] = bi; }
            __syncthreads();
            if (tid == 0) {
                for (int wv = 1; wv < 32; wv++)
                    if (red_v[wv] > red_v[0] ||
                        (red_v[wv] == red_v[0] && red_i[wv] < red_i[0])) {
                        red_v[0] = red_v[wv]; red_i[0] = red_i[wv];
                    }
                int bsel = red_i[0];
                keys[it] = ((unsigned long long)__float_as_uint(red_v[0]) << 32)
                         | (unsigned)(~bsel);
                g_svsc[base + bsel] = NEGV;
            }
            __syncthreads();
        }
    }

    // emit: [boxes 8*100*4][scores 8*100][labels 8*100][keep 8*100]
    const int SC0 = B_IMG * NDET * 4;
    const int LB0 = SC0 + B_IMG * NDET;
    const int KP0 = LB0 + B_IMG * NDET;
    for (int i = tid; i < NDET; i += 1024) {
        float4 bx = make_float4(0.f, 0.f, 0.f, 0.f);
        float sc = 0.0f, lb = 0.0f, kp = 0.0f;
        if (i < nsel) {
            unsigned long long kk = keys[i];
            int j = (int)(~(unsigned)kk);
            bx = g_svbox[base + j];
            sc = __uint_as_float((unsigned)(kk >> 32));
            lb = (float)g_svlab[base + j];
            kp = 1.0f;
        }
        float* ob = out + ((size_t)b * NDET + i) * 4;
        ob[0] = bx.x; ob[1] = bx.y; ob[2] = bx.z; ob[3] = bx.w;
        out[SC0 + b * NDET + i] = sc;
        out[LB0 + b * NDET + i] = lb;
        out[KP0 + b * NDET + i] = kp;
    }
    if (tid == 0) g_svcnt[b] = 0;   // self-reset for next graph replay
}

extern "C" void kernel_launch(void* const* d_in, const int* in_sizes, int n_in,
                              void* d_out, int out_size) {
    const float* logits = (const float*)d_in[0];
    const float* reg    = (const float*)d_in[1];
    const float* props  = (const float*)d_in[2];
    const int*   ih     = (const int*)d_in[3];
    const int*   iw     = (const int*)d_in[4];
    float* out = (float*)d_out;

    phaseA_kernel<<<(B_IMG * NPROP) / 4, 128>>>(logits, reg, props, ih, iw);
    class_nms_kernel<<<dim3(NCM1, B_IMG), 256>>>(ih, iw);
    topk_kernel<<<B_IMG, 1024>>>(out);
}

// round 6
// speedup vs baseline: 6.0487x; 1.0848x over previous
#include <cuda_runtime.h>
#include <cstdint>
#include <math.h>

#define B_IMG 8
#define NPROP 4000
#define NCLS 91
#define NCM1 90
#define CAPC 4000                    // worst-case candidates per (image,class)
#define NDET 100
#define NEGV -1e9f
#define CAPSM 512                    // smem mask-path cap for class NMS
#define NWMAX 8                      // CAPSM/64 mask words per row
#define SV_PER_IMG (NCM1 * NDET)     // 9000 survivors per image (capped)
#define GCAP 1024                    // topk gather capacity
#define HBINS 2048
#define HLO 30720                    // (key>>15) offset; covers scores >~0.0078

static __device__ float4        g_cbox[B_IMG * NCM1 * CAPC];
static __device__ float         g_cs[B_IMG * NCM1 * CAPC];
static __device__ int           g_ccnt[B_IMG * NCM1];        // zero-init, self-reset
static __device__ float4        g_svbox[B_IMG * SV_PER_IMG];
static __device__ float         g_svsc[B_IMG * SV_PER_IMG];
static __device__ unsigned char g_svlab[B_IMG * SV_PER_IMG];
static __device__ int           g_svcnt[B_IMG];              // zero-init, self-reset

__device__ __forceinline__ float load_dim(const int* p) {
    int vi = *p;
    if (vi > 0 && vi < 1000000) return (float)vi;
    return __int_as_float(vi);
}

// ---------------------------------------------------------------------------
// Phase A: one warp per TWO proposals (interleaved chains for ILP).
// Softmax over 91 logits; threshold via multiply; decode only passers;
// compact into per-(image,class) buckets.
// ---------------------------------------------------------------------------
__global__ void __launch_bounds__(256)
phaseA_kernel(const float* __restrict__ logits,
              const float* __restrict__ reg,
              const float* __restrict__ props,
              const int* __restrict__ ph,
              const int* __restrict__ pw) {
    const int q    = blockIdx.x * 8 + (threadIdx.x >> 5);
    const int lane = threadIdx.x & 31;
    if (q >= (B_IMG * NPROP) / 2) return;
    const int p0 = q << 1;

    const float Wf = load_dim(pw);
    const float Hf = load_dim(ph);
    const float CLIPV = 4.135166556742356f;  // log(1000/16)

    const float* z0 = logits + (size_t)p0 * NCLS;
    const float* z1 = z0 + NCLS;

    float a[2][3];
    a[0][0] = z0[lane];  a[1][0] = z1[lane];
    a[0][1] = z0[lane + 32];  a[1][1] = z1[lane + 32];
    a[0][2] = (lane < NCLS - 64) ? z0[lane + 64] : -INFINITY;
    a[1][2] = (lane < NCLS - 64) ? z1[lane + 64] : -INFINITY;

    float m[2];
    #pragma unroll
    for (int k = 0; k < 2; k++) m[k] = fmaxf(fmaxf(a[k][0], a[k][1]), a[k][2]);
    #pragma unroll
    for (int o = 16; o; o >>= 1) {
        #pragma unroll
        for (int k = 0; k < 2; k++)
            m[k] = fmaxf(m[k], __shfl_xor_sync(0xffffffffu, m[k], o));
    }

    float e[2][3], ssum[2];
    #pragma unroll
    for (int k = 0; k < 2; k++) {
        e[k][0] = expf(a[k][0] - m[k]);
        e[k][1] = expf(a[k][1] - m[k]);
        e[k][2] = (lane < NCLS - 64) ? expf(a[k][2] - m[k]) : 0.0f;
        ssum[k] = e[k][0] + e[k][1] + e[k][2];
    }
    #pragma unroll
    for (int o = 16; o; o >>= 1) {
        #pragma unroll
        for (int k = 0; k < 2; k++)
            ssum[k] += __shfl_xor_sync(0xffffffffu, ssum[k], o);
    }

    const float4* prv = (const float4*)props;
    float4 pr[2];
    pr[0] = prv[p0]; pr[1] = prv[p0 + 1];

    #pragma unroll
    for (int k = 0; k < 2; k++) {
        const int p = p0 + k;
        const int b = p / NPROP;
        const float thr = 0.05f * ssum[k];
        float w = pr[k].z - pr[k].x, h = pr[k].w - pr[k].y;
        float cx = pr[k].x + 0.5f * w, cy = pr[k].y + 0.5f * h;
        const float4* rrow = (const float4*)(reg + (size_t)p * (NCLS * 4));

        #pragma unroll
        for (int t = 0; t < 3; t++) {
            int c = lane + 32 * t;
            if (c == 0 || c >= NCLS) continue;
            float ev = e[k][t];
            if (!(ev > thr)) continue;
            float sc = ev / ssum[k];
            float4 r = rrow[c];
            float dx = r.x / 10.0f, dy = r.y / 10.0f;
            float dw = fminf(r.z / 5.0f, CLIPV);
            float dh = fminf(r.w / 5.0f, CLIPV);
            float pcx = dx * w + cx, pcy = dy * h + cy;
            float pwd = expf(dw) * w, phd = expf(dh) * h;
            float x1 = pcx - 0.5f * pwd, y1 = pcy - 0.5f * phd;
            float x2 = pcx + 0.5f * pwd, y2 = pcy + 0.5f * phd;
            x1 = fminf(fmaxf(x1, 0.0f), Wf); x2 = fminf(fmaxf(x2, 0.0f), Wf);
            y1 = fminf(fmaxf(y1, 0.0f), Hf); y2 = fminf(fmaxf(y2, 0.0f), Hf);
            if ((x2 - x1) >= 0.01f && (y2 - y1) >= 0.01f) {
                int bc = b * NCM1 + (c - 1);
                int pos = atomicAdd(&g_ccnt[bc], 1);
                size_t o = (size_t)bc * CAPC + pos;
                g_cbox[o] = make_float4(x1, y1, x2, y2);
                g_cs[o]   = sc;
            }
        }
    }
}

// ---------------------------------------------------------------------------
// Phase B: one block per (image,class). Rank sort (2 barriers), parallel
// O(n^2/2) suppression bitmask (no divisions), register-resident greedy
// bit-scan by thread 0, cap survivors at NDET, append per image.
// ---------------------------------------------------------------------------
__global__ void __launch_bounds__(256)
class_nms_kernel(const int* __restrict__ ph, const int* __restrict__ pw) {
    const int c  = blockIdx.x + 1;
    const int b  = blockIdx.y;
    const int bc = b * NCM1 + (c - 1);
    const int tid = threadIdx.x;
    const int n = g_ccnt[bc];
    if (n == 0) return;

    __shared__ unsigned long long skey[CAPSM];           // 4KB raw keys
    __shared__ unsigned long long ssort[CAPSM];          // 4KB sorted keys
    __shared__ float4             sbox[CAPSM];           // 8KB
    __shared__ unsigned long long mask[CAPSM * NWMAX];   // 32KB suppression bits
    __shared__ unsigned short     surv[NDET];
    __shared__ float              survsc[NDET];
    __shared__ int                nsurv_s, sbase_s;
    __shared__ float              red_v[8];
    __shared__ int                red_i[8];
    __shared__ int                stop_s, seli_s;
    __shared__ float4             selbox_s;

    const float Hf = load_dim(ph);
    const float Wf = load_dim(pw);
    const float off = fmaxf(Hf, Wf) + 1.0f;
    const float t = (float)c * off;
    const size_t base = (size_t)bc * CAPC;

    if (n <= CAPSM) {
        // ---------------- smem mask fast path ----------------
        for (int j = tid; j < n; j += 256)
            skey[j] = ((unsigned long long)__float_as_uint(g_cs[base + j]) << 32)
                    | (unsigned)j;
        __syncthreads();
        // rank sort: keys unique (idx in low bits) => ranks are a permutation
        for (int i = tid; i < n; i += 256) {
            unsigned long long ki = skey[i];
            int r = 0;
            for (int j = 0; j < n; j++) r += (skey[j] > ki);
            ssort[r] = ki;
        }
        __syncthreads();
        for (int i = tid; i < n; i += 256)
            sbox[i] = g_cbox[base + (unsigned)(ssort[i] & 0xffffffffu)];
        __syncthreads();

        // suppression bitmask: mask[i][w] bit j set iff j>i and IoU(i,j) > 0.5.
        // IoU > 0.5  <=>  inter > 0.5*(ai+aj-inter)
        const int NW = (n + 63) >> 6;
        for (int idx = tid; idx < n * NW; idx += 256) {
            int i = idx / NW, w = idx - i * NW;
            unsigned long long bits = 0ull;
            int j0 = w << 6;
            int jend = min(n, j0 + 64);
            int jbeg = max(j0, i + 1);
            if (jbeg < jend) {
                float4 bi = sbox[i];
                float ai = (bi.z - bi.x) * (bi.w - bi.y);
                for (int j = jbeg; j < jend; j++) {
                    float4 bj = sbox[j];
                    float ix1 = fmaxf(bi.x, bj.x), iy1 = fmaxf(bi.y, bj.y);
                    float ix2 = fminf(bi.z, bj.z), iy2 = fminf(bi.w, bj.w);
                    float inter = fmaxf(ix2 - ix1, 0.0f) * fmaxf(iy2 - iy1, 0.0f);
                    float aj = (bj.z - bj.x) * (bj.w - bj.y);
                    if (inter > 0.5f * (ai + aj - inter))
                        bits |= 1ull << (j - j0);
                }
            }
            mask[i * NWMAX + w] = bits;
        }
        __syncthreads();

        // greedy scan, dead-set in registers
        if (tid == 0) {
            unsigned long long dead[NWMAX];
            #pragma unroll
            for (int w = 0; w < NWMAX; w++) dead[w] = 0ull;
            int ns = 0;
            for (int i = 0; i < n && ns < NDET; i++) {
                if ((dead[i >> 6] >> (i & 63)) & 1ull) continue;
                surv[ns] = (unsigned short)i;
                survsc[ns] = __uint_as_float((unsigned)(ssort[i] >> 32));
                ns++;
                for (int w = i >> 6; w < NW; w++) dead[w] |= mask[i * NWMAX + w];
            }
            nsurv_s = ns;
            sbase_s = atomicAdd(&g_svcnt[b], ns);
        }
        __syncthreads();
        const int so = b * SV_PER_IMG + sbase_s;
        for (int s = tid; s < nsurv_s; s += 256) {
            int i = surv[s];
            g_svbox[so + s] = sbox[i];
            g_svsc[so + s]  = survsc[s];
            g_svlab[so + s] = (unsigned char)c;
        }
    } else {
        // ---------------- global fallback (n > 512; essentially never) ------
        __shared__ float gsc_s;
        int ns = 0;
        for (int it = 0; it < NDET; it++) {
            float bv = -2e9f; int bi = 0;
            for (int j = tid; j < n; j += 256) {
                float v = g_cs[base + j];
                if (v > bv) { bv = v; bi = j; }
            }
            #pragma unroll
            for (int o = 16; o; o >>= 1) {
                float ov = __shfl_xor_sync(0xffffffffu, bv, o);
                int   oi = __shfl_xor_sync(0xffffffffu, bi, o);
                if (ov > bv || (ov == bv && oi < bi)) { bv = ov; bi = oi; }
            }
            if ((tid & 31) == 0) { red_v[tid >> 5] = bv; red_i[tid >> 5] = bi; }
            __syncthreads();
            if (tid == 0) {
                for (int wv = 1; wv < 8; wv++)
                    if (red_v[wv] > red_v[0] ||
                        (red_v[wv] == red_v[0] && red_i[wv] < red_i[0])) {
                        red_v[0] = red_v[wv]; red_i[0] = red_i[wv];
                    }
                if (red_v[0] < -5e8f) stop_s = 1;
                else {
                    stop_s = 0; seli_s = red_i[0];
                    selbox_s = g_cbox[base + red_i[0]];
                    gsc_s = red_v[0];
                }
            }
            __syncthreads();
            if (stop_s) break;
            float4 bx = selbox_s;
            float ox1 = bx.x + t, oy1 = bx.y + t, ox2 = bx.z + t, oy2 = bx.w + t;
            float ai = (ox2 - ox1) * (oy2 - oy1);
            for (int j = tid; j < n; j += 256) {
                float v = g_cs[base + j];
                if (v < -5e8f) continue;
                float4 bj = g_cbox[base + j];
                float jx1 = bj.x + t, jy1 = bj.y + t, jx2 = bj.z + t, jy2 = bj.w + t;
                float ix1 = fmaxf(ox1, jx1), iy1 = fmaxf(oy1, jy1);
                float ix2 = fminf(ox2, jx2), iy2 = fminf(oy2, jy2);
                float inter = fmaxf(ix2 - ix1, 0.0f) * fmaxf(iy2 - iy1, 0.0f);
                float aj = (jx2 - jx1) * (jy2 - jy1);
                if (inter > 0.5f * (ai + aj - inter)) g_cs[base + j] = NEGV;
            }
            __syncthreads();
            if (tid == 0) {
                g_cs[base + seli_s] = NEGV;
                int slot = atomicAdd(&g_svcnt[b], 1);
                g_svbox[b * SV_PER_IMG + slot] = selbox_s;
                g_svsc[b * SV_PER_IMG + slot]  = gsc_s;
                g_svlab[b * SV_PER_IMG + slot] = (unsigned char)c;
            }
            ns++;
            __syncthreads();
        }
        (void)ns;
    }
    __syncthreads();
    if (tid == 0) g_ccnt[bc] = 0;   // self-reset for next graph replay
}

// ---------------------------------------------------------------------------
// Phase C: one block per image. Radix-select top-100 of n<=9000 survivors:
// histogram -> 3-barrier hierarchical suffix sum -> pivot -> gather -> rank sort.
// ---------------------------------------------------------------------------
__global__ void __launch_bounds__(1024)
topk_kernel(float* __restrict__ out) {
    const int b   = blockIdx.x;
    const int tid = threadIdx.x;
    const int wid = tid >> 5;
    const int lane = tid & 31;
    const int n   = g_svcnt[b];
    const int base = b * SV_PER_IMG;
    const int nsel = (n < NDET) ? n : NDET;

    __shared__ int hist[HBINS];
    __shared__ int chunksum[32];
    __shared__ int chunksuf[32];
    __shared__ unsigned long long keys[GCAP];
    __shared__ unsigned long long skeys[GCAP];
    __shared__ int gcnt_s, pb_s;

    for (int i = tid; i < HBINS; i += 1024) hist[i] = 0;
    if (tid == 0) { gcnt_s = 0; pb_s = 0; }
    __syncthreads();

    for (int j = tid; j < n; j += 1024) {
        unsigned k = __float_as_uint(g_svsc[base + j]);
        int bkt = (int)(k >> 15) - HLO;
        bkt = max(0, min(HBINS - 1, bkt));
        atomicAdd(&hist[bkt], 1);
    }
    __syncthreads();

    // hierarchical suffix sum over 2048 bins: 32 warps x 64 bins (2 bins/lane)
    int h0 = hist[(wid << 6) + (lane << 1)];
    int h1 = hist[(wid << 6) + (lane << 1) + 1];
    int acc = h0 + h1;
    #pragma unroll
    for (int o = 1; o < 32; o <<= 1) {
        int v = __shfl_down_sync(0xffffffffu, acc, o);
        if (lane + o < 32) acc += v;       // acc = sum of pairs at lanes >= lane
    }
    if (lane == 0) chunksum[wid] = acc;    // chunk total
    __syncthreads();
    if (wid == 0) {
        int cs = chunksum[lane];
        int a2 = cs;
        #pragma unroll
        for (int o = 1; o < 32; o <<= 1) {
            int v = __shfl_down_sync(0xffffffffu, a2, o);
            if (lane + o < 32) a2 += v;    // a2 = sum of chunks >= lane
        }
        chunksuf[lane] = a2 - cs;          // sum of chunks strictly above
    }
    __syncthreads();
    {
        int above = chunksuf[wid];
        hist[(wid << 6) + (lane << 1)]     = above + acc;        // suffix incl bin
        hist[(wid << 6) + (lane << 1) + 1] = above + acc - h0;
    }
    __syncthreads();

    // pivot bucket: largest i with suffix >= nsel
    if (nsel > 0) {
        for (int i = tid; i < HBINS; i += 1024) {
            int s = hist[i];
            int sn = (i + 1 < HBINS) ? hist[i + 1] : 0;
            if (s >= nsel && sn < nsel) pb_s = i;
        }
    }
    __syncthreads();
    const int pb = pb_s;
    const int m  = (nsel > 0) ? hist[pb] : 0;

    if (m <= GCAP) {
        for (int j = tid; j < n; j += 1024) {
            unsigned k = __float_as_uint(g_svsc[base + j]);
            int bkt = (int)(k >> 15) - HLO;
            bkt = max(0, min(HBINS - 1, bkt));
            if (bkt >= pb) {
                int slot = atomicAdd(&gcnt_s, 1);
                keys[slot] = ((unsigned long long)k << 32) | (unsigned)(~j);
            }
        }
        __syncthreads();
        // rank sort descending (keys unique via embedded index)
        for (int i = tid; i < m; i += 1024) {
            unsigned long long ki = keys[i];
            int r = 0;
            for (int j = 0; j < m; j++) r += (keys[j] > ki);
            skeys[r] = ki;
        }
        __syncthreads();
    } else {
        // fallback: destructive argmax loop (pathological tie pile-up only)
        __shared__ float red_v[32];
        __shared__ int   red_i[32];
        for (int it = 0; it < nsel; it++) {
            float bv = -2e9f; int bi = 0;
            for (int j = tid; j < n; j += 1024) {
                float v = g_svsc[base + j];
                if (v > bv) { bv = v; bi = j; }
            }
            #pragma unroll
            for (int o = 16; o; o >>= 1) {
                float ov = __shfl_xor_sync(0xffffffffu, bv, o);
                int   oi = __shfl_xor_sync(0xffffffffu, bi, o);
                if (ov > bv || (ov == bv && oi < bi)) { bv = ov; bi = oi; }
            }
            if ((tid & 31) == 0) { red_v[tid >> 5] = bv; red_i[tid >> 5] = bi; }
            __syncthreads();
            if (tid == 0) {
                for (int wv = 1; wv < 32; wv++)
                    if (red_v[wv] > red_v[0] ||
                        (red_v[wv] == red_v[0] && red_i[wv] < red_i[0])) {
                        red_v[0] = red_v[wv]; red_i[0] = red_i[wv];
                    }
                int bsel = red_i[0];
                skeys[it] = ((unsigned long long)__float_as_uint(red_v[0]) << 32)
                          | (unsigned)(~bsel);
                g_svsc[base + bsel] = NEGV;
            }
            __syncthreads();
        }
    }

    // emit: [boxes 8*100*4][scores 8*100][labels 8*100][keep 8*100]
    const int SC0 = B_IMG * NDET * 4;
    const int LB0 = SC0 + B_IMG * NDET;
    const int KP0 = LB0 + B_IMG * NDET;
    for (int i = tid; i < NDET; i += 1024) {
        float4 bx = make_float4(0.f, 0.f, 0.f, 0.f);
        float sc = 0.0f, lb = 0.0f, kp = 0.0f;
        if (i < nsel) {
            unsigned long long kk = skeys[i];
            int j = (int)(~(unsigned)kk);
            bx = g_svbox[base + j];
            sc = __uint_as_float((unsigned)(kk >> 32));
            lb = (float)g_svlab[base + j];
            kp = 1.0f;
        }
        float* ob = out + ((size_t)b * NDET + i) * 4;
        ob[0] = bx.x; ob[1] = bx.y; ob[2] = bx.z; ob[3] = bx.w;
        out[SC0 + b * NDET + i] = sc;
        out[LB0 + b * NDET + i] = lb;
        out[KP0 + b * NDET + i] = kp;
    }
    if (tid == 0) g_svcnt[b] = 0;   // self-reset for next graph replay
}

extern "C" void kernel_launch(void* const* d_in, const int* in_sizes, int n_in,
                              void* d_out, int out_size) {
    const float* logits = (const float*)d_in[0];
    const float* reg    = (const float*)d_in[1];
    const float* props  = (const float*)d_in[2];
    const int*   ih     = (const int*)d_in[3];
    const int*   iw     = (const int*)d_in[4];
    float* out = (float*)d_out;

    phaseA_kernel<<<(B_IMG * NPROP) / 16, 256>>>(logits, reg, props, ih, iw);
    class_nms_kernel<<<dim3(NCM1, B_IMG), 256>>>(ih, iw);
    topk_kernel<<<B_IMG, 1024>>>(out);
}

// round 7
// speedup vs baseline: 6.7632x; 1.1181x over previous
#include <cuda_runtime.h>
#include <cstdint>
#include <math.h>

#define B_IMG 8
#define NPROP 4000
#define NCLS 91
#define NCM1 90
#define CAPC 4000                    // worst-case candidates per (image,class)
#define NDET 100
#define NEGV -1e9f
#define CAPSM 512                    // smem sort cap for class NMS
#define MASKN 320                    // mask-path cap (NW <= 5)
#define NWM 5                        // mask words per row
#define SV_PER_IMG (NCM1 * NDET)     // 9000 survivors per image (capped)
#define GCAP 1024                    // topk gather capacity
#define HBINS 2048
#define HLO 30720                    // (key>>15) offset; covers scores >~0.0078

static __device__ float4        g_cbox[B_IMG * NCM1 * CAPC];
static __device__ float         g_cs[B_IMG * NCM1 * CAPC];
static __device__ int           g_ccnt[B_IMG * NCM1];        // zero-init, self-reset
static __device__ float4        g_svbox[B_IMG * SV_PER_IMG];
static __device__ float         g_svsc[B_IMG * SV_PER_IMG];
static __device__ unsigned char g_svlab[B_IMG * SV_PER_IMG];
static __device__ int           g_svcnt[B_IMG];              // zero-init, self-reset

__device__ __forceinline__ float load_dim(const int* p) {
    int vi = *p;
    if (vi > 0 && vi < 1000000) return (float)vi;
    return __int_as_float(vi);
}

// ---------------------------------------------------------------------------
// Phase A: one warp per TWO proposals. NO max-subtract (softmax is shift
// invariant; logits bounded) -> EX2s issue right after loads, single
// sum-reduction chain. __expf everywhere (1 MUFU op, no fixup tail).
// ---------------------------------------------------------------------------
__global__ void __launch_bounds__(256)
phaseA_kernel(const float* __restrict__ logits,
              const float* __restrict__ reg,
              const float* __restrict__ props,
              const int* __restrict__ ph,
              const int* __restrict__ pw) {
    const int q    = blockIdx.x * 8 + (threadIdx.x >> 5);
    const int lane = threadIdx.x & 31;
    if (q >= (B_IMG * NPROP) / 2) return;
    const int p0 = q << 1;

    const float Wf = load_dim(pw);
    const float Hf = load_dim(ph);
    const float CLIPV = 4.135166556742356f;  // log(1000/16)

    const float* z0 = logits + (size_t)p0 * NCLS;
    const float* z1 = z0 + NCLS;

    // exps start as soon as each load lands; two independent chains
    float e[2][3];
    e[0][0] = __expf(z0[lane]);
    e[1][0] = __expf(z1[lane]);
    e[0][1] = __expf(z0[lane + 32]);
    e[1][1] = __expf(z1[lane + 32]);
    e[0][2] = (lane < NCLS - 64) ? __expf(z0[lane + 64]) : 0.0f;
    e[1][2] = (lane < NCLS - 64) ? __expf(z1[lane + 64]) : 0.0f;

    float ssum[2];
    ssum[0] = e[0][0] + e[0][1] + e[0][2];
    ssum[1] = e[1][0] + e[1][1] + e[1][2];
    #pragma unroll
    for (int o = 16; o; o >>= 1) {
        ssum[0] += __shfl_xor_sync(0xffffffffu, ssum[0], o);
        ssum[1] += __shfl_xor_sync(0xffffffffu, ssum[1], o);
    }

    const float4* prv = (const float4*)props;
    float4 pr[2];
    pr[0] = prv[p0]; pr[1] = prv[p0 + 1];

    #pragma unroll
    for (int k = 0; k < 2; k++) {
        const int p = p0 + k;
        const int b = p / NPROP;
        const float thr = 0.05f * ssum[k];
        float w = pr[k].z - pr[k].x, h = pr[k].w - pr[k].y;
        float cx = pr[k].x + 0.5f * w, cy = pr[k].y + 0.5f * h;
        const float4* rrow = (const float4*)(reg + (size_t)p * (NCLS * 4));

        #pragma unroll
        for (int t = 0; t < 3; t++) {
            int c = lane + 32 * t;
            if (c == 0 || c >= NCLS) continue;
            float ev = e[k][t];
            if (!(ev > thr)) continue;
            float sc = ev / ssum[k];
            float4 r = rrow[c];
            float dx = r.x / 10.0f, dy = r.y / 10.0f;
            float dw = fminf(r.z / 5.0f, CLIPV);
            float dh = fminf(r.w / 5.0f, CLIPV);
            float pcx = dx * w + cx, pcy = dy * h + cy;
            float pwd = __expf(dw) * w, phd = __expf(dh) * h;
            float x1 = pcx - 0.5f * pwd, y1 = pcy - 0.5f * phd;
            float x2 = pcx + 0.5f * pwd, y2 = pcy + 0.5f * phd;
            x1 = fminf(fmaxf(x1, 0.0f), Wf); x2 = fminf(fmaxf(x2, 0.0f), Wf);
            y1 = fminf(fmaxf(y1, 0.0f), Hf); y2 = fminf(fmaxf(y2, 0.0f), Hf);
            if ((x2 - x1) >= 0.01f && (y2 - y1) >= 0.01f) {
                int bc = b * NCM1 + (c - 1);
                int pos = atomicAdd(&g_ccnt[bc], 1);
                size_t o = (size_t)bc * CAPC + pos;
                g_cbox[o] = make_float4(x1, y1, x2, y2);
                g_cs[o]   = sc;
            }
        }
    }
}

// ---------------------------------------------------------------------------
// Phase B: one block per (image,class). Rank sort (2 barriers). Three paths:
//   n <= MASKN : parallel suppression bitmask + register greedy bit-scan
//   n <= CAPSM : maskless warp-greedy on sorted smem
//   else       : global argmax greedy (essentially never)
// ~30KB smem -> 7 blocks/SM -> single wave of 720 blocks.
// ---------------------------------------------------------------------------
__global__ void __launch_bounds__(256)
class_nms_kernel(const int* __restrict__ ph, const int* __restrict__ pw) {
    const int c  = blockIdx.x + 1;
    const int b  = blockIdx.y;
    const int bc = b * NCM1 + (c - 1);
    const int tid = threadIdx.x;
    const int n = g_ccnt[bc];
    if (n == 0) return;

    __shared__ unsigned long long skey[CAPSM];           // 4KB raw keys
    __shared__ unsigned long long ssort[CAPSM];          // 4KB sorted keys
    __shared__ float4             sbox[CAPSM];           // 8KB
    __shared__ unsigned long long mask[MASKN * NWM];     // 12.5KB suppression bits
    __shared__ unsigned char      alive[CAPSM];          // 0.5KB (mid path)
    __shared__ unsigned short     surv[NDET];
    __shared__ float              survsc[NDET];
    __shared__ int                nsurv_s, sbase_s;
    __shared__ float              red_v[8];
    __shared__ int                red_i[8];
    __shared__ int                stop_s, seli_s;
    __shared__ float4             selbox_s;
    __shared__ float              gsc_s;

    const float Hf = load_dim(ph);
    const float Wf = load_dim(pw);
    const float off = fmaxf(Hf, Wf) + 1.0f;
    const float t = (float)c * off;
    const size_t base = (size_t)bc * CAPC;

    if (n <= CAPSM) {
        // ---- shared rank sort (keys unique via embedded index) ----
        for (int j = tid; j < n; j += 256)
            skey[j] = ((unsigned long long)__float_as_uint(g_cs[base + j]) << 32)
                    | (unsigned)j;
        __syncthreads();
        for (int i = tid; i < n; i += 256) {
            unsigned long long ki = skey[i];
            int r = 0;
            for (int j = 0; j < n; j++) r += (skey[j] > ki);
            ssort[r] = ki;
        }
        __syncthreads();
        for (int i = tid; i < n; i += 256)
            sbox[i] = g_cbox[base + (unsigned)(ssort[i] & 0xffffffffu)];

        if (n <= MASKN) {
            // ---- mask path ----
            __syncthreads();
            const int NW = (n + 63) >> 6;
            for (int idx = tid; idx < n * NW; idx += 256) {
                int i = idx / NW, w = idx - i * NW;
                unsigned long long bits = 0ull;
                int j0 = w << 6;
                int jend = min(n, j0 + 64);
                int jbeg = max(j0, i + 1);
                if (jbeg < jend) {
                    float4 bi = sbox[i];
                    float ai = (bi.z - bi.x) * (bi.w - bi.y);
                    for (int j = jbeg; j < jend; j++) {
                        float4 bj = sbox[j];
                        float ix1 = fmaxf(bi.x, bj.x), iy1 = fmaxf(bi.y, bj.y);
                        float ix2 = fminf(bi.z, bj.z), iy2 = fminf(bi.w, bj.w);
                        float inter = fmaxf(ix2 - ix1, 0.0f) * fmaxf(iy2 - iy1, 0.0f);
                        float aj = (bj.z - bj.x) * (bj.w - bj.y);
                        if (inter > 0.5f * (ai + aj - inter))
                            bits |= 1ull << (j - j0);
                    }
                }
                mask[i * NWM + w] = bits;
            }
            __syncthreads();
            if (tid == 0) {
                unsigned long long dead[NWM];
                #pragma unroll
                for (int w = 0; w < NWM; w++) dead[w] = 0ull;
                int ns = 0;
                for (int i = 0; i < n && ns < NDET; i++) {
                    if ((dead[i >> 6] >> (i & 63)) & 1ull) continue;
                    surv[ns] = (unsigned short)i;
                    survsc[ns] = __uint_as_float((unsigned)(ssort[i] >> 32));
                    ns++;
                    for (int w = i >> 6; w < NW; w++) dead[w] |= mask[i * NWM + w];
                }
                nsurv_s = ns;
                sbase_s = atomicAdd(&g_svcnt[b], ns);
            }
        } else {
            // ---- maskless warp-greedy mid path (320 < n <= 512) ----
            for (int i = tid; i < n; i += 256) alive[i] = 1;
            __syncthreads();
            if (tid < 32) {
                int ns = 0;
                for (int i = 0; i < n && ns < NDET; i++) {
                    if (alive[i] == 0) continue;
                    if (tid == 0) {
                        surv[ns] = (unsigned short)i;
                        survsc[ns] = __uint_as_float((unsigned)(ssort[i] >> 32));
                    }
                    ns++;
                    float4 bi = sbox[i];
                    float ai = (bi.z - bi.x) * (bi.w - bi.y);
                    for (int j = i + 1 + tid; j < n; j += 32) {
                        if (!alive[j]) continue;
                        float4 bj = sbox[j];
                        float ix1 = fmaxf(bi.x, bj.x), iy1 = fmaxf(bi.y, bj.y);
                        float ix2 = fminf(bi.z, bj.z), iy2 = fminf(bi.w, bj.w);
                        float inter = fmaxf(ix2 - ix1, 0.0f) * fmaxf(iy2 - iy1, 0.0f);
                        float aj = (bj.z - bj.x) * (bj.w - bj.y);
                        if (inter > 0.5f * (ai + aj - inter)) alive[j] = 0;
                    }
                    __syncwarp();
                }
                if (tid == 0) {
                    nsurv_s = ns;
                    sbase_s = atomicAdd(&g_svcnt[b], ns);
                }
            }
        }
        __syncthreads();
        const int so = b * SV_PER_IMG + sbase_s;
        for (int s = tid; s < nsurv_s; s += 256) {
            int i = surv[s];
            g_svbox[so + s] = sbox[i];
            g_svsc[so + s]  = survsc[s];
            g_svlab[so + s] = (unsigned char)c;
        }
    } else {
        // ---- global fallback (n > 512; essentially never) ----
        for (int it = 0; it < NDET; it++) {
            float bv = -2e9f; int bi = 0;
            for (int j = tid; j < n; j += 256) {
                float v = g_cs[base + j];
                if (v > bv) { bv = v; bi = j; }
            }
            #pragma unroll
            for (int o = 16; o; o >>= 1) {
                float ov = __shfl_xor_sync(0xffffffffu, bv, o);
                int   oi = __shfl_xor_sync(0xffffffffu, bi, o);
                if (ov > bv || (ov == bv && oi < bi)) { bv = ov; bi = oi; }
            }
            if ((tid & 31) == 0) { red_v[tid >> 5] = bv; red_i[tid >> 5] = bi; }
            __syncthreads();
            if (tid == 0) {
                for (int wv = 1; wv < 8; wv++)
                    if (red_v[wv] > red_v[0] ||
                        (red_v[wv] == red_v[0] && red_i[wv] < red_i[0])) {
                        red_v[0] = red_v[wv]; red_i[0] = red_i[wv];
                    }
                if (red_v[0] < -5e8f) stop_s = 1;
                else {
                    stop_s = 0; seli_s = red_i[0];
                    selbox_s = g_cbox[base + red_i[0]];
                    gsc_s = red_v[0];
                }
            }
            __syncthreads();
            if (stop_s) break;
            float4 bx = selbox_s;
            float ox1 = bx.x + t, oy1 = bx.y + t, ox2 = bx.z + t, oy2 = bx.w + t;
            float ai = (ox2 - ox1) * (oy2 - oy1);
            for (int j = tid; j < n; j += 256) {
                float v = g_cs[base + j];
                if (v < -5e8f) continue;
                float4 bj = g_cbox[base + j];
                float jx1 = bj.x + t, jy1 = bj.y + t, jx2 = bj.z + t, jy2 = bj.w + t;
                float ix1 = fmaxf(ox1, jx1), iy1 = fmaxf(oy1, jy1);
                float ix2 = fminf(ox2, jx2), iy2 = fminf(oy2, jy2);
                float inter = fmaxf(ix2 - ix1, 0.0f) * fmaxf(iy2 - iy1, 0.0f);
                float aj = (jx2 - jx1) * (jy2 - jy1);
                if (inter > 0.5f * (ai + aj - inter)) g_cs[base + j] = NEGV;
            }
            __syncthreads();
            if (tid == 0) {
                g_cs[base + seli_s] = NEGV;
                int slot = atomicAdd(&g_svcnt[b], 1);
                g_svbox[b * SV_PER_IMG + slot] = selbox_s;
                g_svsc[b * SV_PER_IMG + slot]  = gsc_s;
                g_svlab[b * SV_PER_IMG + slot] = (unsigned char)c;
            }
            __syncthreads();
        }
    }
    __syncthreads();
    if (tid == 0) g_ccnt[bc] = 0;   // self-reset for next graph replay
}

// ---------------------------------------------------------------------------
// Phase C: one block per image. Radix-select top-100 of survivors:
// histogram -> 3-barrier hierarchical suffix sum -> pivot -> gather -> rank sort.
// ---------------------------------------------------------------------------
__global__ void __launch_bounds__(1024)
topk_kernel(float* __restrict__ out) {
    const int b   = blockIdx.x;
    const int tid = threadIdx.x;
    const int wid = tid >> 5;
    const int lane = tid & 31;
    const int n   = g_svcnt[b];
    const int base = b * SV_PER_IMG;
    const int nsel = (n < NDET) ? n : NDET;

    __shared__ int hist[HBINS];
    __shared__ int chunksum[32];
    __shared__ int chunksuf[32];
    __shared__ unsigned long long keys[GCAP];
    __shared__ unsigned long long skeys[GCAP];
    __shared__ int gcnt_s, pb_s;

    for (int i = tid; i < HBINS; i += 1024) hist[i] = 0;
    if (tid == 0) { gcnt_s = 0; pb_s = 0; }
    __syncthreads();

    for (int j = tid; j < n; j += 1024) {
        unsigned k = __float_as_uint(g_svsc[base + j]);
        int bkt = (int)(k >> 15) - HLO;
        bkt = max(0, min(HBINS - 1, bkt));
        atomicAdd(&hist[bkt], 1);
    }
    __syncthreads();

    // hierarchical suffix sum over 2048 bins: 32 warps x 64 bins (2 bins/lane)
    int h0 = hist[(wid << 6) + (lane << 1)];
    int h1 = hist[(wid << 6) + (lane << 1) + 1];
    int acc = h0 + h1;
    #pragma unroll
    for (int o = 1; o < 32; o <<= 1) {
        int v = __shfl_down_sync(0xffffffffu, acc, o);
        if (lane + o < 32) acc += v;
    }
    if (lane == 0) chunksum[wid] = acc;
    __syncthreads();
    if (wid == 0) {
        int cs = chunksum[lane];
        int a2 = cs;
        #pragma unroll
        for (int o = 1; o < 32; o <<= 1) {
            int v = __shfl_down_sync(0xffffffffu, a2, o);
            if (lane + o < 32) a2 += v;
        }
        chunksuf[lane] = a2 - cs;
    }
    __syncthreads();
    {
        int above = chunksuf[wid];
        hist[(wid << 6) + (lane << 1)]     = above + acc;
        hist[(wid << 6) + (lane << 1) + 1] = above + acc - h0;
    }
    __syncthreads();

    if (nsel > 0) {
        for (int i = tid; i < HBINS; i += 1024) {
            int s = hist[i];
            int sn = (i + 1 < HBINS) ? hist[i + 1] : 0;
            if (s >= nsel && sn < nsel) pb_s = i;
        }
    }
    __syncthreads();
    const int pb = pb_s;
    const int m  = (nsel > 0) ? hist[pb] : 0;

    if (m <= GCAP) {
        for (int j = tid; j < n; j += 1024) {
            unsigned k = __float_as_uint(g_svsc[base + j]);
            int bkt = (int)(k >> 15) - HLO;
            bkt = max(0, min(HBINS - 1, bkt));
            if (bkt >= pb) {
                int slot = atomicAdd(&gcnt_s, 1);
                keys[slot] = ((unsigned long long)k << 32) | (unsigned)(~j);
            }
        }
        __syncthreads();
        for (int i = tid; i < m; i += 1024) {
            unsigned long long ki = keys[i];
            int r = 0;
            for (int j = 0; j < m; j++) r += (keys[j] > ki);
            skeys[r] = ki;
        }
        __syncthreads();
    } else {
        __shared__ float red_v[32];
        __shared__ int   red_i[32];
        for (int it = 0; it < nsel; it++) {
            float bv = -2e9f; int bi = 0;
            for (int j = tid; j < n; j += 1024) {
                float v = g_svsc[base + j];
                if (v > bv) { bv = v; bi = j; }
            }
            #pragma unroll
            for (int o = 16; o; o >>= 1) {
                float ov = __shfl_xor_sync(0xffffffffu, bv, o);
                int   oi = __shfl_xor_sync(0xffffffffu, bi, o);
                if (ov > bv || (ov == bv && oi < bi)) { bv = ov; bi = oi; }
            }
            if ((tid & 31) == 0) { red_v[tid >> 5] = bv; red_i[tid >> 5] = bi; }
            __syncthreads();
            if (tid == 0) {
                for (int wv = 1; wv < 32; wv++)
                    if (red_v[wv] > red_v[0] ||
                        (red_v[wv] == red_v[0] && red_i[wv] < red_i[0])) {
                        red_v[0] = red_v[wv]; red_i[0] = red_i[wv];
                    }
                int bsel = red_i[0];
                skeys[it] = ((unsigned long long)__float_as_uint(red_v[0]) << 32)
                          | (unsigned)(~bsel);
                g_svsc[base + bsel] = NEGV;
            }
            __syncthreads();
        }
    }

    // emit: [boxes 8*100*4][scores 8*100][labels 8*100][keep 8*100]
    const int SC0 = B_IMG * NDET * 4;
    const int LB0 = SC0 + B_IMG * NDET;
    const int KP0 = LB0 + B_IMG * NDET;
    for (int i = tid; i < NDET; i += 1024) {
        float4 bx = make_float4(0.f, 0.f, 0.f, 0.f);
        float sc = 0.0f, lb = 0.0f, kp = 0.0f;
        if (i < nsel) {
            unsigned long long kk = skeys[i];
            int j = (int)(~(unsigned)kk);
            bx = g_svbox[base + j];
            sc = __uint_as_float((unsigned)(kk >> 32));
            lb = (float)g_svlab[base + j];
            kp = 1.0f;
        }
        float* ob = out + ((size_t)b * NDET + i) * 4;
        ob[0] = bx.x; ob[1] = bx.y; ob[2] = bx.z; ob[3] = bx.w;
        out[SC0 + b * NDET + i] = sc;
        out[LB0 + b * NDET + i] = lb;
        out[KP0 + b * NDET + i] = kp;
    }
    if (tid == 0) g_svcnt[b] = 0;   // self-reset for next graph replay
}

extern "C" void kernel_launch(void* const* d_in, const int* in_sizes, int n_in,
                              void* d_out, int out_size) {
    const float* logits = (const float*)d_in[0];
    const float* reg    = (const float*)d_in[1];
    const float* props  = (const float*)d_in[2];
    const int*   ih     = (const int*)d_in[3];
    const int*   iw     = (const int*)d_in[4];
    float* out = (float*)d_out;

    phaseA_kernel<<<(B_IMG * NPROP) / 16, 256>>>(logits, reg, props, ih, iw);
    class_nms_kernel<<<dim3(NCM1, B_IMG), 256>>>(ih, iw);
    topk_kernel<<<B_IMG, 1024>>>(out);
}

// round 8
// speedup vs baseline: 7.9887x; 1.1812x over previous
#include <cuda_runtime.h>
#include <cstdint>
#include <math.h>

#define B_IMG 8
#define NPROP 4000
#define NCLS 91
#define NCM1 90
#define CAPC 4000                    // worst-case candidates per (image,class)
#define NDET 100
#define NEGV -1e9f
#define CAPSM 512                    // smem sort cap for class NMS
#define MASKN 320                    // mask-path cap (NW <= 5)
#define NWM 5                        // mask words per row
#define SV_PER_IMG (NCM1 * NDET)     // 9000 survivors per image (capped)
#define GCAP 1024                    // topk gather capacity
#define HBINS 2048
#define HLO 30720                    // (key>>15) offset; covers scores >~0.0078
#define NBLKA 2000                   // phaseA blocks (16 proposals each)
#define QCAP 320                     // per-block queue cap (<=20 passers/proposal)

static __device__ float4             g_cbox[B_IMG * NCM1 * CAPC];
static __device__ float              g_cs[B_IMG * NCM1 * CAPC];
static __device__ int                g_ccnt[B_IMG * NCM1];    // zero-init, self-reset
static __device__ unsigned long long g_q[NBLKA * QCAP];
static __device__ int                g_qcnt[NBLKA];           // zero-init, self-reset
static __device__ float4             g_svbox[B_IMG * SV_PER_IMG];
static __device__ float              g_svsc[B_IMG * SV_PER_IMG];
static __device__ unsigned char      g_svlab[B_IMG * SV_PER_IMG];
static __device__ int                g_svcnt[B_IMG];          // zero-init, self-reset

__device__ __forceinline__ float load_dim(const int* p) {
    int vi = *p;
    if (vi > 0 && vi < 1000000) return (float)vi;
    return __int_as_float(vi);
}

// ---------------------------------------------------------------------------
// Phase A: pure softmax + threshold filter. One warp per TWO proposals.
// Passers are appended to a per-block queue (smem counter, no global atomics),
// as u64 {score_bits, (p<<7)|c}. Decode is deferred to decode_kernel.
// ---------------------------------------------------------------------------
__global__ void __launch_bounds__(256)
phaseA_kernel(const float* __restrict__ logits) {
    const int warp = threadIdx.x >> 5;
    const int lane = threadIdx.x & 31;
    const int p0 = (blockIdx.x * 8 + warp) << 1;

    __shared__ int s_cnt;
    if (threadIdx.x == 0) s_cnt = 0;
    __syncthreads();

    const float* z0 = logits + (size_t)p0 * NCLS;
    const float* z1 = z0 + NCLS;

    float e[2][3];
    e[0][0] = __expf(z0[lane]);
    e[1][0] = __expf(z1[lane]);
    e[0][1] = __expf(z0[lane + 32]);
    e[1][1] = __expf(z1[lane + 32]);
    e[0][2] = (lane < NCLS - 64) ? __expf(z0[lane + 64]) : 0.0f;
    e[1][2] = (lane < NCLS - 64) ? __expf(z1[lane + 64]) : 0.0f;

    float ssum[2];
    ssum[0] = e[0][0] + e[0][1] + e[0][2];
    ssum[1] = e[1][0] + e[1][1] + e[1][2];
    #pragma unroll
    for (int o = 16; o; o >>= 1) {
        ssum[0] += __shfl_xor_sync(0xffffffffu, ssum[0], o);
        ssum[1] += __shfl_xor_sync(0xffffffffu, ssum[1], o);
    }

    const unsigned long long qbase = (unsigned long long)blockIdx.x * QCAP;

    #pragma unroll
    for (int k = 0; k < 2; k++) {
        const float thr = 0.05f * ssum[k];
        #pragma unroll
        for (int t = 0; t < 3; t++) {
            int c = lane + 32 * t;
            bool pass = (c > 0) && (c < NCLS) && (e[k][t] > thr);
            unsigned mask = __ballot_sync(0xffffffffu, pass);
            if (mask) {
                int leader = __ffs(mask) - 1;
                int pos = 0;
                if (lane == leader) pos = atomicAdd(&s_cnt, __popc(mask));
                pos = __shfl_sync(0xffffffffu, pos, leader);
                if (pass) {
                    int rank = __popc(mask & ((1u << lane) - 1u));
                    float sc = e[k][t] / ssum[k];
                    unsigned idx = ((unsigned)(p0 + k) << 7) | (unsigned)c;
                    g_q[qbase + pos + rank] =
                        ((unsigned long long)__float_as_uint(sc) << 32) | idx;
                }
            }
        }
    }
    __syncthreads();
    if (threadIdx.x == 0) g_qcnt[blockIdx.x] = s_cnt;
}

// ---------------------------------------------------------------------------
// Decode: one thread per queued candidate (dense, full MLP). Box decode,
// clip, size filter, compact into per-(image,class) buckets.
// ---------------------------------------------------------------------------
__global__ void __launch_bounds__(128)
decode_kernel(const float* __restrict__ reg,
              const float* __restrict__ props,
              const int* __restrict__ ph,
              const int* __restrict__ pw) {
    const int bid = blockIdx.x;
    const int cnt = g_qcnt[bid];
    const float Wf = load_dim(pw);
    const float Hf = load_dim(ph);
    const float CLIPV = 4.135166556742356f;  // log(1000/16)

    for (int i = threadIdx.x; i < cnt; i += 128) {
        unsigned long long en = g_q[(unsigned long long)bid * QCAP + i];
        float sc = __uint_as_float((unsigned)(en >> 32));
        unsigned idx = (unsigned)en;
        int p = idx >> 7, c = idx & 127;

        float4 pr = ((const float4*)props)[p];
        float w = pr.z - pr.x, h = pr.w - pr.y;
        float cx = pr.x + 0.5f * w, cy = pr.y + 0.5f * h;
        float4 r = ((const float4*)reg)[p * NCLS + c];

        float dx = r.x / 10.0f, dy = r.y / 10.0f;
        float dw = fminf(r.z / 5.0f, CLIPV);
        float dh = fminf(r.w / 5.0f, CLIPV);
        float pcx = dx * w + cx, pcy = dy * h + cy;
        float pwd = __expf(dw) * w, phd = __expf(dh) * h;
        float x1 = pcx - 0.5f * pwd, y1 = pcy - 0.5f * phd;
        float x2 = pcx + 0.5f * pwd, y2 = pcy + 0.5f * phd;
        x1 = fminf(fmaxf(x1, 0.0f), Wf); x2 = fminf(fmaxf(x2, 0.0f), Wf);
        y1 = fminf(fmaxf(y1, 0.0f), Hf); y2 = fminf(fmaxf(y2, 0.0f), Hf);
        if ((x2 - x1) >= 0.01f && (y2 - y1) >= 0.01f) {
            int b = p / NPROP;
            int bc = b * NCM1 + (c - 1);
            int pos = atomicAdd(&g_ccnt[bc], 1);
            size_t o = (size_t)bc * CAPC + pos;
            g_cbox[o] = make_float4(x1, y1, x2, y2);
            g_cs[o]   = sc;
        }
    }
    if (threadIdx.x == 0) g_qcnt[bid] = 0;   // self-reset for next replay
}

// ---------------------------------------------------------------------------
// Phase B: one block per (image,class). Rank sort (2 barriers). Three paths:
//   n <= MASKN : parallel suppression bitmask + register greedy bit-scan
//   n <= CAPSM : maskless warp-greedy on sorted smem
//   else       : global argmax greedy (essentially never)
// ---------------------------------------------------------------------------
__global__ void __launch_bounds__(256)
class_nms_kernel(const int* __restrict__ ph, const int* __restrict__ pw) {
    const int c  = blockIdx.x + 1;
    const int b  = blockIdx.y;
    const int bc = b * NCM1 + (c - 1);
    const int tid = threadIdx.x;
    const int n = g_ccnt[bc];
    if (n == 0) return;

    __shared__ unsigned long long skey[CAPSM];
    __shared__ unsigned long long ssort[CAPSM];
    __shared__ float4             sbox[CAPSM];
    __shared__ unsigned long long mask[MASKN * NWM];
    __shared__ unsigned char      alive[CAPSM];
    __shared__ unsigned short     surv[NDET];
    __shared__ float              survsc[NDET];
    __shared__ int                nsurv_s, sbase_s;
    __shared__ float              red_v[8];
    __shared__ int                red_i[8];
    __shared__ int                stop_s, seli_s;
    __shared__ float4             selbox_s;
    __shared__ float              gsc_s;

    const float Hf = load_dim(ph);
    const float Wf = load_dim(pw);
    const float off = fmaxf(Hf, Wf) + 1.0f;
    const float t = (float)c * off;
    const size_t base = (size_t)bc * CAPC;

    if (n <= CAPSM) {
        for (int j = tid; j < n; j += 256)
            skey[j] = ((unsigned long long)__float_as_uint(g_cs[base + j]) << 32)
                    | (unsigned)j;
        __syncthreads();
        for (int i = tid; i < n; i += 256) {
            unsigned long long ki = skey[i];
            int r = 0;
            for (int j = 0; j < n; j++) r += (skey[j] > ki);
            ssort[r] = ki;
        }
        __syncthreads();
        for (int i = tid; i < n; i += 256)
            sbox[i] = g_cbox[base + (unsigned)(ssort[i] & 0xffffffffu)];

        if (n <= MASKN) {
            __syncthreads();
            const int NW = (n + 63) >> 6;
            for (int idx = tid; idx < n * NW; idx += 256) {
                int i = idx / NW, w = idx - i * NW;
                unsigned long long bits = 0ull;
                int j0 = w << 6;
                int jend = min(n, j0 + 64);
                int jbeg = max(j0, i + 1);
                if (jbeg < jend) {
                    float4 bi = sbox[i];
                    float ai = (bi.z - bi.x) * (bi.w - bi.y);
                    for (int j = jbeg; j < jend; j++) {
                        float4 bj = sbox[j];
                        float ix1 = fmaxf(bi.x, bj.x), iy1 = fmaxf(bi.y, bj.y);
                        float ix2 = fminf(bi.z, bj.z), iy2 = fminf(bi.w, bj.w);
                        float inter = fmaxf(ix2 - ix1, 0.0f) * fmaxf(iy2 - iy1, 0.0f);
                        float aj = (bj.z - bj.x) * (bj.w - bj.y);
                        if (inter > 0.5f * (ai + aj - inter))
                            bits |= 1ull << (j - j0);
                    }
                }
                mask[i * NWM + w] = bits;
            }
            __syncthreads();
            if (tid == 0) {
                unsigned long long dead[NWM];
                #pragma unroll
                for (int w = 0; w < NWM; w++) dead[w] = 0ull;
                int ns = 0;
                for (int i = 0; i < n && ns < NDET; i++) {
                    if ((dead[i >> 6] >> (i & 63)) & 1ull) continue;
                    surv[ns] = (unsigned short)i;
                    survsc[ns] = __uint_as_float((unsigned)(ssort[i] >> 32));
                    ns++;
                    for (int w = i >> 6; w < NW; w++) dead[w] |= mask[i * NWM + w];
                }
                nsurv_s = ns;
                sbase_s = atomicAdd(&g_svcnt[b], ns);
            }
        } else {
            for (int i = tid; i < n; i += 256) alive[i] = 1;
            __syncthreads();
            if (tid < 32) {
                int ns = 0;
                for (int i = 0; i < n && ns < NDET; i++) {
                    if (alive[i] == 0) continue;
                    if (tid == 0) {
                        surv[ns] = (unsigned short)i;
                        survsc[ns] = __uint_as_float((unsigned)(ssort[i] >> 32));
                    }
                    ns++;
                    float4 bi = sbox[i];
                    float ai = (bi.z - bi.x) * (bi.w - bi.y);
                    for (int j = i + 1 + tid; j < n; j += 32) {
                        if (!alive[j]) continue;
                        float4 bj = sbox[j];
                        float ix1 = fmaxf(bi.x, bj.x), iy1 = fmaxf(bi.y, bj.y);
                        float ix2 = fminf(bi.z, bj.z), iy2 = fminf(bi.w, bj.w);
                        float inter = fmaxf(ix2 - ix1, 0.0f) * fmaxf(iy2 - iy1, 0.0f);
                        float aj = (bj.z - bj.x) * (bj.w - bj.y);
                        if (inter > 0.5f * (ai + aj - inter)) alive[j] = 0;
                    }
                    __syncwarp();
                }
                if (tid == 0) {
                    nsurv_s = ns;
                    sbase_s = atomicAdd(&g_svcnt[b], ns);
                }
            }
        }
        __syncthreads();
        const int so = b * SV_PER_IMG + sbase_s;
        for (int s = tid; s < nsurv_s; s += 256) {
            int i = surv[s];
            g_svbox[so + s] = sbox[i];
            g_svsc[so + s]  = survsc[s];
            g_svlab[so + s] = (unsigned char)c;
        }
    } else {
        for (int it = 0; it < NDET; it++) {
            float bv = -2e9f; int bi = 0;
            for (int j = tid; j < n; j += 256) {
                float v = g_cs[base + j];
                if (v > bv) { bv = v; bi = j; }
            }
            #pragma unroll
            for (int o = 16; o; o >>= 1) {
                float ov = __shfl_xor_sync(0xffffffffu, bv, o);
                int   oi = __shfl_xor_sync(0xffffffffu, bi, o);
                if (ov > bv || (ov == bv && oi < bi)) { bv = ov; bi = oi; }
            }
            if ((tid & 31) == 0) { red_v[tid >> 5] = bv; red_i[tid >> 5] = bi; }
            __syncthreads();
            if (tid == 0) {
                for (int wv = 1; wv < 8; wv++)
                    if (red_v[wv] > red_v[0] ||
                        (red_v[wv] == red_v[0] && red_i[wv] < red_i[0])) {
                        red_v[0] = red_v[wv]; red_i[0] = red_i[wv];
                    }
                if (red_v[0] < -5e8f) stop_s = 1;
                else {
                    stop_s = 0; seli_s = red_i[0];
                    selbox_s = g_cbox[base + red_i[0]];
                    gsc_s = red_v[0];
                }
            }
            __syncthreads();
            if (stop_s) break;
            float4 bx = selbox_s;
            float ox1 = bx.x + t, oy1 = bx.y + t, ox2 = bx.z + t, oy2 = bx.w + t;
            float ai = (ox2 - ox1) * (oy2 - oy1);
            for (int j = tid; j < n; j += 256) {
                float v = g_cs[base + j];
                if (v < -5e8f) continue;
                float4 bj = g_cbox[base + j];
                float jx1 = bj.x + t, jy1 = bj.y + t, jx2 = bj.z + t, jy2 = bj.w + t;
                float ix1 = fmaxf(ox1, jx1), iy1 = fmaxf(oy1, jy1);
                float ix2 = fminf(ox2, jx2), iy2 = fminf(oy2, jy2);
                float inter = fmaxf(ix2 - ix1, 0.0f) * fmaxf(iy2 - iy1, 0.0f);
                float aj = (jx2 - jx1) * (jy2 - jy1);
                if (inter > 0.5f * (ai + aj - inter)) g_cs[base + j] = NEGV;
            }
            __syncthreads();
            if (tid == 0) {
                g_cs[base + seli_s] = NEGV;
                int slot = atomicAdd(&g_svcnt[b], 1);
                g_svbox[b * SV_PER_IMG + slot] = selbox_s;
                g_svsc[b * SV_PER_IMG + slot]  = gsc_s;
                g_svlab[b * SV_PER_IMG + slot] = (unsigned char)c;
            }
            __syncthreads();
        }
    }
    __syncthreads();
    if (tid == 0) g_ccnt[bc] = 0;   // self-reset for next graph replay
}

// ---------------------------------------------------------------------------
// Phase C: one block per image. Radix-select top-100 of survivors.
// ---------------------------------------------------------------------------
__global__ void __launch_bounds__(1024)
topk_kernel(float* __restrict__ out) {
    const int b   = blockIdx.x;
    const int tid = threadIdx.x;
    const int wid = tid >> 5;
    const int lane = tid & 31;
    const int n   = g_svcnt[b];
    const int base = b * SV_PER_IMG;
    const int nsel = (n < NDET) ? n : NDET;

    __shared__ int hist[HBINS];
    __shared__ int chunksum[32];
    __shared__ int chunksuf[32];
    __shared__ unsigned long long keys[GCAP];
    __shared__ unsigned long long skeys[GCAP];
    __shared__ int gcnt_s, pb_s;

    for (int i = tid; i < HBINS; i += 1024) hist[i] = 0;
    if (tid == 0) { gcnt_s = 0; pb_s = 0; }
    __syncthreads();

    for (int j = tid; j < n; j += 1024) {
        unsigned k = __float_as_uint(g_svsc[base + j]);
        int bkt = (int)(k >> 15) - HLO;
        bkt = max(0, min(HBINS - 1, bkt));
        atomicAdd(&hist[bkt], 1);
    }
    __syncthreads();

    int h0 = hist[(wid << 6) + (lane << 1)];
    int h1 = hist[(wid << 6) + (lane << 1) + 1];
    int acc = h0 + h1;
    #pragma unroll
    for (int o = 1; o < 32; o <<= 1) {
        int v = __shfl_down_sync(0xffffffffu, acc, o);
        if (lane + o < 32) acc += v;
    }
    if (lane == 0) chunksum[wid] = acc;
    __syncthreads();
    if (wid == 0) {
        int cs = chunksum[lane];
        int a2 = cs;
        #pragma unroll
        for (int o = 1; o < 32; o <<= 1) {
            int v = __shfl_down_sync(0xffffffffu, a2, o);
            if (lane + o < 32) a2 += v;
        }
        chunksuf[lane] = a2 - cs;
    }
    __syncthreads();
    {
        int above = chunksuf[wid];
        hist[(wid << 6) + (lane << 1)]     = above + acc;
        hist[(wid << 6) + (lane << 1) + 1] = above + acc - h0;
    }
    __syncthreads();

    if (nsel > 0) {
        for (int i = tid; i < HBINS; i += 1024) {
            int s = hist[i];
            int sn = (i + 1 < HBINS) ? hist[i + 1] : 0;
            if (s >= nsel && sn < nsel) pb_s = i;
        }
    }
    __syncthreads();
    const int pb = pb_s;
    const int m  = (nsel > 0) ? hist[pb] : 0;

    if (m <= GCAP) {
        for (int j = tid; j < n; j += 1024) {
            unsigned k = __float_as_uint(g_svsc[base + j]);
            int bkt = (int)(k >> 15) - HLO;
            bkt = max(0, min(HBINS - 1, bkt));
            if (bkt >= pb) {
                int slot = atomicAdd(&gcnt_s, 1);
                keys[slot] = ((unsigned long long)k << 32) | (unsigned)(~j);
            }
        }
        __syncthreads();
        for (int i = tid; i < m; i += 1024) {
            unsigned long long ki = keys[i];
            int r = 0;
            for (int j = 0; j < m; j++) r += (keys[j] > ki);
            skeys[r] = ki;
        }
        __syncthreads();
    } else {
        __shared__ float red_v[32];
        __shared__ int   red_i[32];
        for (int it = 0; it < nsel; it++) {
            float bv = -2e9f; int bi = 0;
            for (int j = tid; j < n; j += 1024) {
                float v = g_svsc[base + j];
                if (v > bv) { bv = v; bi = j; }
            }
            #pragma unroll
            for (int o = 16; o; o >>= 1) {
                float ov = __shfl_xor_sync(0xffffffffu, bv, o);
                int   oi = __shfl_xor_sync(0xffffffffu, bi, o);
                if (ov > bv || (ov == bv && oi < bi)) { bv = ov; bi = oi; }
            }
            if ((tid & 31) == 0) { red_v[tid >> 5] = bv; red_i[tid >> 5] = bi; }
            __syncthreads();
            if (tid == 0) {
                for (int wv = 1; wv < 32; wv++)
                    if (red_v[wv] > red_v[0] ||
                        (red_v[wv] == red_v[0] && red_i[wv] < red_i[0])) {
                        red_v[0] = red_v[wv]; red_i[0] = red_i[wv];
                    }
                int bsel = red_i[0];
                skeys[it] = ((unsigned long long)__float_as_uint(red_v[0]) << 32)
                          | (unsigned)(~bsel);
                g_svsc[base + bsel] = NEGV;
            }
            __syncthreads();
        }
    }

    // emit: [boxes 8*100*4][scores 8*100][labels 8*100][keep 8*100]
    const int SC0 = B_IMG * NDET * 4;
    const int LB0 = SC0 + B_IMG * NDET;
    const int KP0 = LB0 + B_IMG * NDET;
    for (int i = tid; i < NDET; i += 1024) {
        float4 bx = make_float4(0.f, 0.f, 0.f, 0.f);
        float sc = 0.0f, lb = 0.0f, kp = 0.0f;
        if (i < nsel) {
            unsigned long long kk = skeys[i];
            int j = (int)(~(unsigned)kk);
            bx = g_svbox[base + j];
            sc = __uint_as_float((unsigned)(kk >> 32));
            lb = (float)g_svlab[base + j];
            kp = 1.0f;
        }
        float* ob = out + ((size_t)b * NDET + i) * 4;
        ob[0] = bx.x; ob[1] = bx.y; ob[2] = bx.z; ob[3] = bx.w;
        out[SC0 + b * NDET + i] = sc;
        out[LB0 + b * NDET + i] = lb;
        out[KP0 + b * NDET + i] = kp;
    }
    if (tid == 0) g_svcnt[b] = 0;   // self-reset for next graph replay
}

extern "C" void kernel_launch(void* const* d_in, const int* in_sizes, int n_in,
                              void* d_out, int out_size) {
    const float* logits = (const float*)d_in[0];
    const float* reg    = (const float*)d_in[1];
    const float* props  = (const float*)d_in[2];
    const int*   ih     = (const int*)d_in[3];
    const int*   iw     = (const int*)d_in[4];
    float* out = (float*)d_out;

    phaseA_kernel<<<NBLKA, 256>>>(logits);
    decode_kernel<<<NBLKA, 128>>>(reg, props, ih, iw);
    class_nms_kernel<<<dim3(NCM1, B_IMG), 256>>>(ih, iw);
    topk_kernel<<<B_IMG, 1024>>>(out);
}

// round 9
// speedup vs baseline: 8.4043x; 1.0520x over previous
#include <cuda_runtime.h>
#include <cstdint>
#include <math.h>

#define B_IMG 8
#define NPROP 4000
#define NCLS 91
#define NCM1 90
#define CAPC 4000                    // worst-case candidates per (image,class)
#define NDET 100
#define NEGV -1e9f
#define CAPSM 512                    // smem sort cap for class NMS
#define MASKN 320                    // mask-path cap (NW <= 5)
#define NWM 5                        // mask words per row
#define SV_PER_IMG (NCM1 * NDET)     // 9000 survivors per image (capped)
#define GCAP 1024                    // topk gather capacity
#define HBINS 2048
#define HLO 30720                    // (key>>15) offset; covers scores >~0.0078
#define NBLKA 2000                   // phaseAB blocks (16 proposals each)
#define QCAP 320                     // smem queue cap (<=20 passers/proposal)

static __device__ float4        g_cbox[B_IMG * NCM1 * CAPC];
static __device__ float         g_cs[B_IMG * NCM1 * CAPC];
static __device__ int           g_ccnt[B_IMG * NCM1];    // zero-init, self-reset
static __device__ float4        g_svbox[B_IMG * SV_PER_IMG];
static __device__ float         g_svsc[B_IMG * SV_PER_IMG];
static __device__ unsigned char g_svlab[B_IMG * SV_PER_IMG];
static __device__ int           g_svcnt[B_IMG];          // zero-init, self-reset
static __device__ int           g_hist[B_IMG * HBINS];   // zero-init, topk re-zeros

__device__ __forceinline__ float load_dim(const int* p) {
    int vi = *p;
    if (vi > 0 && vi < 1000000) return (float)vi;
    return __int_as_float(vi);
}

__device__ __forceinline__ int score_bkt(unsigned keybits) {
    int bkt = (int)(keybits >> 15) - HLO;
    return max(0, min(HBINS - 1, bkt));
}

// ---------------------------------------------------------------------------
// Phase AB (fused): phase 1 = softmax + threshold filter, passers queued in
// SMEM (warp prefix-scan, one smem atomic per warp). phase 2 = dense decode
// of the queue by all 256 threads (full MLP, no divergent tail in phase 1).
// ---------------------------------------------------------------------------
__global__ void __launch_bounds__(256)
phaseAB_kernel(const float* __restrict__ logits,
               const float* __restrict__ reg,
               const float* __restrict__ props,
               const int* __restrict__ ph,
               const int* __restrict__ pw) {
    const int warp = threadIdx.x >> 5;
    const int lane = threadIdx.x & 31;
    const int p0 = (blockIdx.x * 8 + warp) << 1;

    __shared__ unsigned long long q[QCAP];
    __shared__ int s_cnt;
    if (threadIdx.x == 0) s_cnt = 0;
    __syncthreads();

    const float* z0 = logits + (size_t)p0 * NCLS;
    const float* z1 = z0 + NCLS;

    float e[2][3];
    e[0][0] = __expf(z0[lane]);
    e[1][0] = __expf(z1[lane]);
    e[0][1] = __expf(z0[lane + 32]);
    e[1][1] = __expf(z1[lane + 32]);
    e[0][2] = (lane < NCLS - 64) ? __expf(z0[lane + 64]) : 0.0f;
    e[1][2] = (lane < NCLS - 64) ? __expf(z1[lane + 64]) : 0.0f;

    float ssum[2];
    ssum[0] = e[0][0] + e[0][1] + e[0][2];
    ssum[1] = e[1][0] + e[1][1] + e[1][2];
    #pragma unroll
    for (int o = 16; o; o >>= 1) {
        ssum[0] += __shfl_xor_sync(0xffffffffu, ssum[0], o);
        ssum[1] += __shfl_xor_sync(0xffffffffu, ssum[1], o);
    }

    // per-thread pass flags for the 6 (k,t) slots, fully unrolled (registers)
    bool pass[6];
    int cnt = 0;
    #pragma unroll
    for (int k = 0; k < 2; k++) {
        float thr = 0.05f * ssum[k];
        #pragma unroll
        for (int t = 0; t < 3; t++) {
            int c = lane + 32 * t;
            bool pk = (c > 0) && (c < NCLS) && (e[k][t] > thr);
            pass[k * 3 + t] = pk;
            cnt += pk ? 1 : 0;
        }
    }

    // warp inclusive scan of cnt; one smem atomic per warp
    int incl = cnt;
    #pragma unroll
    for (int o = 1; o < 32; o <<= 1) {
        int v = __shfl_up_sync(0xffffffffu, incl, o);
        if (lane >= o) incl += v;
    }
    int total = __shfl_sync(0xffffffffu, incl, 31);
    int wbase = 0;
    if (total > 0) {
        if (lane == 31) wbase = atomicAdd(&s_cnt, total);
        wbase = __shfl_sync(0xffffffffu, wbase, 31);
        int off = wbase + incl - cnt;
        #pragma unroll
        for (int k = 0; k < 2; k++) {
            #pragma unroll
            for (int t = 0; t < 3; t++) {
                if (pass[k * 3 + t]) {
                    int c = lane + 32 * t;
                    float sc = e[k][t] / ssum[k];
                    unsigned idx = ((unsigned)(p0 + k) << 7) | (unsigned)c;
                    q[off++] = ((unsigned long long)__float_as_uint(sc) << 32) | idx;
                }
            }
        }
    }
    __syncthreads();

    // ---- phase 2: dense decode of the smem queue ----
    const int qcnt = s_cnt;
    const float Wf = load_dim(pw);
    const float Hf = load_dim(ph);
    const float CLIPV = 4.135166556742356f;  // log(1000/16)

    for (int i = threadIdx.x; i < qcnt; i += 256) {
        unsigned long long en = q[i];
        float sc = __uint_as_float((unsigned)(en >> 32));
        unsigned idx = (unsigned)en;
        int p = idx >> 7, c = idx & 127;

        float4 pr = ((const float4*)props)[p];
        float w = pr.z - pr.x, h = pr.w - pr.y;
        float cx = pr.x + 0.5f * w, cy = pr.y + 0.5f * h;
        float4 r = ((const float4*)reg)[p * NCLS + c];

        float dx = r.x / 10.0f, dy = r.y / 10.0f;
        float dw = fminf(r.z / 5.0f, CLIPV);
        float dh = fminf(r.w / 5.0f, CLIPV);
        float pcx = dx * w + cx, pcy = dy * h + cy;
        float pwd = __expf(dw) * w, phd = __expf(dh) * h;
        float x1 = pcx - 0.5f * pwd, y1 = pcy - 0.5f * phd;
        float x2 = pcx + 0.5f * pwd, y2 = pcy + 0.5f * phd;
        x1 = fminf(fmaxf(x1, 0.0f), Wf); x2 = fminf(fmaxf(x2, 0.0f), Wf);
        y1 = fminf(fmaxf(y1, 0.0f), Hf); y2 = fminf(fmaxf(y2, 0.0f), Hf);
        if ((x2 - x1) >= 0.01f && (y2 - y1) >= 0.01f) {
            int b = p / NPROP;
            int bc = b * NCM1 + (c - 1);
            int pos = atomicAdd(&g_ccnt[bc], 1);
            size_t o = (size_t)bc * CAPC + pos;
            g_cbox[o] = make_float4(x1, y1, x2, y2);
            g_cs[o]   = sc;
        }
    }
}

// ---------------------------------------------------------------------------
// Phase B: one block per (image,class). Rank sort (2 barriers), suppression
// bitmask + register greedy scan (n<=MASKN), warp-greedy (n<=CAPSM), global
// argmax fallback. Survivors appended per image; their score-buckets are
// accumulated into the per-image global histogram (pre-computing topk's work).
// ---------------------------------------------------------------------------
__global__ void __launch_bounds__(256)
class_nms_kernel(const int* __restrict__ ph, const int* __restrict__ pw) {
    const int c  = blockIdx.x + 1;
    const int b  = blockIdx.y;
    const int bc = b * NCM1 + (c - 1);
    const int tid = threadIdx.x;
    const int n = g_ccnt[bc];
    if (n == 0) return;

    __shared__ unsigned long long skey[CAPSM];
    __shared__ unsigned long long ssort[CAPSM];
    __shared__ float4             sbox[CAPSM];
    __shared__ unsigned long long mask[MASKN * NWM];
    __shared__ unsigned char      alive[CAPSM];
    __shared__ unsigned short     surv[NDET];
    __shared__ float              survsc[NDET];
    __shared__ int                nsurv_s, sbase_s;
    __shared__ float              red_v[8];
    __shared__ int                red_i[8];
    __shared__ int                stop_s, seli_s;
    __shared__ float4             selbox_s;
    __shared__ float              gsc_s;

    const float Hf = load_dim(ph);
    const float Wf = load_dim(pw);
    const float off = fmaxf(Hf, Wf) + 1.0f;
    const float t = (float)c * off;
    const size_t base = (size_t)bc * CAPC;

    if (n <= CAPSM) {
        for (int j = tid; j < n; j += 256)
            skey[j] = ((unsigned long long)__float_as_uint(g_cs[base + j]) << 32)
                    | (unsigned)j;
        __syncthreads();
        for (int i = tid; i < n; i += 256) {
            unsigned long long ki = skey[i];
            int r = 0;
            for (int j = 0; j < n; j++) r += (skey[j] > ki);
            ssort[r] = ki;
        }
        __syncthreads();
        for (int i = tid; i < n; i += 256)
            sbox[i] = g_cbox[base + (unsigned)(ssort[i] & 0xffffffffu)];

        if (n <= MASKN) {
            __syncthreads();
            const int NW = (n + 63) >> 6;
            for (int idx = tid; idx < n * NW; idx += 256) {
                int i = idx / NW, w = idx - i * NW;
                unsigned long long bits = 0ull;
                int j0 = w << 6;
                int jend = min(n, j0 + 64);
                int jbeg = max(j0, i + 1);
                if (jbeg < jend) {
                    float4 bi = sbox[i];
                    float ai = (bi.z - bi.x) * (bi.w - bi.y);
                    for (int j = jbeg; j < jend; j++) {
                        float4 bj = sbox[j];
                        float ix1 = fmaxf(bi.x, bj.x), iy1 = fmaxf(bi.y, bj.y);
                        float ix2 = fminf(bi.z, bj.z), iy2 = fminf(bi.w, bj.w);
                        float inter = fmaxf(ix2 - ix1, 0.0f) * fmaxf(iy2 - iy1, 0.0f);
                        float aj = (bj.z - bj.x) * (bj.w - bj.y);
                        if (inter > 0.5f * (ai + aj - inter))
                            bits |= 1ull << (j - j0);
                    }
                }
                mask[i * NWM + w] = bits;
            }
            __syncthreads();
            if (tid == 0) {
                unsigned long long dead[NWM];
                #pragma unroll
                for (int w = 0; w < NWM; w++) dead[w] = 0ull;
                int ns = 0;
                for (int i = 0; i < n && ns < NDET; i++) {
                    if ((dead[i >> 6] >> (i & 63)) & 1ull) continue;
                    surv[ns] = (unsigned short)i;
                    survsc[ns] = __uint_as_float((unsigned)(ssort[i] >> 32));
                    ns++;
                    for (int w = i >> 6; w < NW; w++) dead[w] |= mask[i * NWM + w];
                }
                nsurv_s = ns;
                sbase_s = atomicAdd(&g_svcnt[b], ns);
            }
        } else {
            for (int i = tid; i < n; i += 256) alive[i] = 1;
            __syncthreads();
            if (tid < 32) {
                int ns = 0;
                for (int i = 0; i < n && ns < NDET; i++) {
                    if (alive[i] == 0) continue;
                    if (tid == 0) {
                        surv[ns] = (unsigned short)i;
                        survsc[ns] = __uint_as_float((unsigned)(ssort[i] >> 32));
                    }
                    ns++;
                    float4 bi = sbox[i];
                    float ai = (bi.z - bi.x) * (bi.w - bi.y);
                    for (int j = i + 1 + tid; j < n; j += 32) {
                        if (!alive[j]) continue;
                        float4 bj = sbox[j];
                        float ix1 = fmaxf(bi.x, bj.x), iy1 = fmaxf(bi.y, bj.y);
                        float ix2 = fminf(bi.z, bj.z), iy2 = fminf(bi.w, bj.w);
                        float inter = fmaxf(ix2 - ix1, 0.0f) * fmaxf(iy2 - iy1, 0.0f);
                        float aj = (bj.z - bj.x) * (bj.w - bj.y);
                        if (inter > 0.5f * (ai + aj - inter)) alive[j] = 0;
                    }
                    __syncwarp();
                }
                if (tid == 0) {
                    nsurv_s = ns;
                    sbase_s = atomicAdd(&g_svcnt[b], ns);
                }
            }
        }
        __syncthreads();
        const int so = b * SV_PER_IMG + sbase_s;
        for (int s = tid; s < nsurv_s; s += 256) {
            int i = surv[s];
            float sv = survsc[s];
            g_svbox[so + s] = sbox[i];
            g_svsc[so + s]  = sv;
            g_svlab[so + s] = (unsigned char)c;
            atomicAdd(&g_hist[b * HBINS + score_bkt(__float_as_uint(sv))], 1);
        }
    } else {
        for (int it = 0; it < NDET; it++) {
            float bv = -2e9f; int bi = 0;
            for (int j = tid; j < n; j += 256) {
                float v = g_cs[base + j];
                if (v > bv) { bv = v; bi = j; }
            }
            #pragma unroll
            for (int o = 16; o; o >>= 1) {
                float ov = __shfl_xor_sync(0xffffffffu, bv, o);
                int   oi = __shfl_xor_sync(0xffffffffu, bi, o);
                if (ov > bv || (ov == bv && oi < bi)) { bv = ov; bi = oi; }
            }
            if ((tid & 31) == 0) { red_v[tid >> 5] = bv; red_i[tid >> 5] = bi; }
            __syncthreads();
            if (tid == 0) {
                for (int wv = 1; wv < 8; wv++)
                    if (red_v[wv] > red_v[0] ||
                        (red_v[wv] == red_v[0] && red_i[wv] < red_i[0])) {
                        red_v[0] = red_v[wv]; red_i[0] = red_i[wv];
                    }
                if (red_v[0] < -5e8f) stop_s = 1;
                else {
                    stop_s = 0; seli_s = red_i[0];
                    selbox_s = g_cbox[base + red_i[0]];
                    gsc_s = red_v[0];
                }
            }
            __syncthreads();
            if (stop_s) break;
            float4 bx = selbox_s;
            float ox1 = bx.x + t, oy1 = bx.y + t, ox2 = bx.z + t, oy2 = bx.w + t;
            float ai = (ox2 - ox1) * (oy2 - oy1);
            for (int j = tid; j < n; j += 256) {
                float v = g_cs[base + j];
                if (v < -5e8f) continue;
                float4 bj = g_cbox[base + j];
                float jx1 = bj.x + t, jy1 = bj.y + t, jx2 = bj.z + t, jy2 = bj.w + t;
                float ix1 = fmaxf(ox1, jx1), iy1 = fmaxf(oy1, jy1);
                float ix2 = fminf(ox2, jx2), iy2 = fminf(oy2, jy2);
                float inter = fmaxf(ix2 - ix1, 0.0f) * fmaxf(iy2 - iy1, 0.0f);
                float aj = (jx2 - jx1) * (jy2 - jy1);
                if (inter > 0.5f * (ai + aj - inter)) g_cs[base + j] = NEGV;
            }
            __syncthreads();
            if (tid == 0) {
                g_cs[base + seli_s] = NEGV;
                int slot = atomicAdd(&g_svcnt[b], 1);
                g_svbox[b * SV_PER_IMG + slot] = selbox_s;
                g_svsc[b * SV_PER_IMG + slot]  = gsc_s;
                g_svlab[b * SV_PER_IMG + slot] = (unsigned char)c;
                atomicAdd(&g_hist[b * HBINS + score_bkt(__float_as_uint(gsc_s))], 1);
            }
            __syncthreads();
        }
    }
    __syncthreads();
    if (tid == 0) g_ccnt[bc] = 0;   // self-reset for next graph replay
}

// ---------------------------------------------------------------------------
// Phase C: one block per image. Histogram comes precomputed from class_nms;
// suffix sum -> pivot -> gather -> rank sort -> emit. Re-zeros g_hist.
// ---------------------------------------------------------------------------
__global__ void __launch_bounds__(1024)
topk_kernel(float* __restrict__ out) {
    const int b   = blockIdx.x;
    const int tid = threadIdx.x;
    const int wid = tid >> 5;
    const int lane = tid & 31;
    const int n   = g_svcnt[b];
    const int base = b * SV_PER_IMG;
    const int nsel = (n < NDET) ? n : NDET;

    __shared__ int hist[HBINS];
    __shared__ int chunksum[32];
    __shared__ int chunksuf[32];
    __shared__ unsigned long long keys[GCAP];
    __shared__ unsigned long long skeys[GCAP];
    __shared__ int gcnt_s, pb_s;

    // load precomputed histogram; re-zero global copy for next replay
    for (int i = tid; i < HBINS; i += 1024) {
        hist[i] = g_hist[b * HBINS + i];
        g_hist[b * HBINS + i] = 0;
    }
    if (tid == 0) { gcnt_s = 0; pb_s = 0; }
    __syncthreads();

    int h0 = hist[(wid << 6) + (lane << 1)];
    int h1 = hist[(wid << 6) + (lane << 1) + 1];
    int acc = h0 + h1;
    #pragma unroll
    for (int o = 1; o < 32; o <<= 1) {
        int v = __shfl_down_sync(0xffffffffu, acc, o);
        if (lane + o < 32) acc += v;
    }
    if (lane == 0) chunksum[wid] = acc;
    __syncthreads();
    if (wid == 0) {
        int cs = chunksum[lane];
        int a2 = cs;
        #pragma unroll
        for (int o = 1; o < 32; o <<= 1) {
            int v = __shfl_down_sync(0xffffffffu, a2, o);
            if (lane + o < 32) a2 += v;
        }
        chunksuf[lane] = a2 - cs;
    }
    __syncthreads();
    {
        int above = chunksuf[wid];
        hist[(wid << 6) + (lane << 1)]     = above + acc;
        hist[(wid << 6) + (lane << 1) + 1] = above + acc - h0;
    }
    __syncthreads();

    if (nsel > 0) {
        for (int i = tid; i < HBINS; i += 1024) {
            int s = hist[i];
            int sn = (i + 1 < HBINS) ? hist[i + 1] : 0;
            if (s >= nsel && sn < nsel) pb_s = i;
        }
    }
    __syncthreads();
    const int pb = pb_s;
    const int m  = (nsel > 0) ? hist[pb] : 0;

    if (m <= GCAP) {
        for (int j = tid; j < n; j += 1024) {
            unsigned k = __float_as_uint(g_svsc[base + j]);
            if (score_bkt(k) >= pb) {
                int slot = atomicAdd(&gcnt_s, 1);
                keys[slot] = ((unsigned long long)k << 32) | (unsigned)(~j);
            }
        }
        __syncthreads();
        for (int i = tid; i < m; i += 1024) {
            unsigned long long ki = keys[i];
            int r = 0;
            for (int j = 0; j < m; j++) r += (keys[j] > ki);
            skeys[r] = ki;
        }
        __syncthreads();
    } else {
        __shared__ float red_v[32];
        __shared__ int   red_i[32];
        for (int it = 0; it < nsel; it++) {
            float bv = -2e9f; int bi = 0;
            for (int j = tid; j < n; j += 1024) {
                float v = g_svsc[base + j];
                if (v > bv) { bv = v; bi = j; }
            }
            #pragma unroll
            for (int o = 16; o; o >>= 1) {
                float ov = __shfl_xor_sync(0xffffffffu, bv, o);
                int   oi = __shfl_xor_sync(0xffffffffu, bi, o);
                if (ov > bv || (ov == bv && oi < bi)) { bv = ov; bi = oi; }
            }
            if ((tid & 31) == 0) { red_v[tid >> 5] = bv; red_i[tid >> 5] = bi; }
            __syncthreads();
            if (tid == 0) {
                for (int wv = 1; wv < 32; wv++)
                    if (red_v[wv] > red_v[0] ||
                        (red_v[wv] == red_v[0] && red_i[wv] < red_i[0])) {
                        red_v[0] = red_v[wv]; red_i[0] = red_i[wv];
                    }
                int bsel = red_i[0];
                skeys[it] = ((unsigned long long)__float_as_uint(red_v[0]) << 32)
                          | (unsigned)(~bsel);
                g_svsc[base + bsel] = NEGV;
            }
            __syncthreads();
        }
    }

    // emit: [boxes 8*100*4][scores 8*100][labels 8*100][keep 8*100]
    const int SC0 = B_IMG * NDET * 4;
    const int LB0 = SC0 + B_IMG * NDET;
    const int KP0 = LB0 + B_IMG * NDET;
    for (int i = tid; i < NDET; i += 1024) {
        float4 bx = make_float4(0.f, 0.f, 0.f, 0.f);
        float sc = 0.0f, lb = 0.0f, kp = 0.0f;
        if (i < nsel) {
            unsigned long long kk = skeys[i];
            int j = (int)(~(unsigned)kk);
            bx = g_svbox[base + j];
            sc = __uint_as_float((unsigned)(kk >> 32));
            lb = (float)g_svlab[base + j];
            kp = 1.0f;
        }
        float* ob = out + ((size_t)b * NDET + i) * 4;
        ob[0] = bx.x; ob[1] = bx.y; ob[2] = bx.z; ob[3] = bx.w;
        out[SC0 + b * NDET + i] = sc;
        out[LB0 + b * NDET + i] = lb;
        out[KP0 + b * NDET + i] = kp;
    }
    if (tid == 0) g_svcnt[b] = 0;   // self-reset for next graph replay
}

extern "C" void kernel_launch(void* const* d_in, const int* in_sizes, int n_in,
                              void* d_out, int out_size) {
    const float* logits = (const float*)d_in[0];
    const float* reg    = (const float*)d_in[1];
    const float* props  = (const float*)d_in[2];
    const int*   ih     = (const int*)d_in[3];
    const int*   iw     = (const int*)d_in[4];
    float* out = (float*)d_out;

    phaseAB_kernel<<<NBLKA, 256>>>(logits, reg, props, ih, iw);
    class_nms_kernel<<<dim3(NCM1, B_IMG), 256>>>(ih, iw);
    topk_kernel<<<B_IMG, 1024>>>(out);
}